// round 8
// baseline (speedup 1.0000x reference)
#include <cuda_runtime.h>
#include <math.h>

// ---------------- problem constants ----------------
#define BATCH 8
#define SEQL 512
#define NFEAT 16
#define DMODEL 512
#define FDIM 256          // L/2
#define HID 1024          // 4*F
#define NEXP 43
#define TOPK 5
#define TOTROWS 1657
#define EMB_ELEMS 108593152LL   // 8*16*1657*512
#define KS1 16            // k-split for mlp1 (256/16 = 16 per block)
#define KS2 32            // h-split for mlp2 (1024/32 = 32 per block)

__constant__ int c_P[NEXP] = {
  2,3,4,5,6,7,8,9,10,11,12,13,14,15,16,17,18,19,20,21,22,23,24,25,26,
  28,30,32,34,36,39,42,46,51,56,64,73,85,102,128,170,256,512};
__constant__ int c_OFF[NEXP+1] = {
  0,256,427,555,658,744,818,882,939,991,1038,1081,1121,1158,1193,1225,
  1256,1285,1312,1338,1363,1387,1410,1432,1453,1473,1492,1510,1526,1542,
  1557,1571,1584,1596,1607,1617,1625,1633,1640,1646,1650,1654,1656,1657};

// ---------------- device scratch ----------------
__device__ float g_xr[BATCH][FDIM];
__device__ float g_xi[BATCH][FDIM];
__device__ float g_p1r[KS1][BATCH][HID];    // mlp1 partials
__device__ float g_p1i[KS1][BATCH][HID];
__device__ float g_p2r[KS2][BATCH][FDIM];   // mlp2 partials
__device__ float g_p2i[KS2][BATCH][FDIM];
__device__ float g_mask[BATCH][NEXP];
__device__ float g_feat[NFEAT][256];   // first half of d_model, depends on c
__device__ float g_pos[256][256];      // second half, depends on patch idx j
__device__ unsigned int g_ctr = 0;     // last-block ticket for fused gating

// ---------------- K1: gate1 (blocks 0-7) + pos tables (blocks 8-143) -------
__global__ void __launch_bounds__(512)
gate1_pos_kernel(const float* __restrict__ x,
                 const float* __restrict__ w_start,
                 const float* __restrict__ b_start) {
    if (blockIdx.x >= 8) {
        // positional tables, fp64 to match numpy
        int idx = (blockIdx.x - 8) * 512 + threadIdx.x;   // 0 .. 69631
        if (idx < NFEAT * 256) {
            int c = idx >> 8, i = idx & 255;
            double div = pow(10000.0, (double)(2 * (i >> 1)) / 256.0);
            double a = (double)c / div;
            g_feat[c][i] = (float)((i & 1) ? cos(a) : sin(a));
        } else {
            int k2 = idx - NFEAT * 256;
            int j = k2 >> 8, i = k2 & 255;
            double div = pow(10000.0, (double)(2 * (i >> 1)) / 256.0);
            double a = (double)j / div;
            g_pos[j][i] = (float)((i & 1) ? cos(a) : sin(a));
        }
        return;
    }
    // ---- gate1: start_fc + direct rFFT (ortho, drop DC), 512 threads ----
    __shared__ float xs[SEQL];
    __shared__ float2 tw[SEQL];
    __shared__ float2 ps[SEQL];
    __shared__ float ws[NFEAT];
    int b = blockIdx.x, t = threadIdx.x;
    if (t < NFEAT) ws[t] = w_start[t];
    {
        float s, c;
        sincospif((float)t * (1.0f / 256.0f), &s, &c);  // angle = 2*pi*t/512
        tw[t] = make_float2(c, s);
    }
    __syncthreads();
    {
        const float* xp = x + (((size_t)b * SEQL + t) << 4);
        float s = b_start[0];
        #pragma unroll
        for (int c = 0; c < NFEAT; c++) s = fmaf(xp[c], ws[c], s);
        xs[t] = s;
    }
    __syncthreads();
    int k  = (t & 255) + 1;                          // k = 1..256 (DC dropped)
    int l0 = (t >> 8) << 8;                          // 0 or 256
    float re = 0.f, im = 0.f;
    int m = (k * l0) & 511;
    #pragma unroll 8
    for (int i = 0; i < 256; i++) {
        float xv = xs[l0 + i];
        float2 w = tw[m];
        re = fmaf(xv,  w.x, re);
        im = fmaf(xv, -w.y, im);
        m = (m + k) & 511;
    }
    ps[t] = make_float2(re, im);
    __syncthreads();
    if (t < 256) {
        const float sc = 0.04419417382415922f;       // 1/sqrt(512)
        float2 lo = ps[t], hi = ps[t + 256];
        g_xr[b][t] = (lo.x + hi.x) * sc;
        g_xi[b][t] = (lo.y + hi.y) * sc;
    }
}

// ---------------- K2: complex layer 1 partials (all batches per thread) ----
// grid (HID/256=4, KS1=16), 256 threads. Each thread: one h, 16-k slice, 8 b.
__global__ void __launch_bounds__(256)
mlp1_part_kernel(const float* __restrict__ w1) {
    const int kz = blockIdx.y;
    const int h  = blockIdx.x * 256 + threadIdx.x;   // 0..1023
    const int KSL = FDIM / KS1;                      // 16
    const int k0 = kz * KSL;
    __shared__ float sxr[BATCH][KSL], sxi[BATCH][KSL];
    if (threadIdx.x < BATCH * KSL) {
        int b = threadIdx.x >> 4, k = threadIdx.x & 15;
        sxr[b][k] = g_xr[b][k0 + k];
        sxi[b][k] = g_xi[b][k0 + k];
    }
    __syncthreads();
    const float* w1r = w1 + (size_t)k0 * HID;
    const float* w1i = w1 + (size_t)(FDIM + k0) * HID;
    float ar[BATCH], ai[BATCH];
    #pragma unroll
    for (int b = 0; b < BATCH; b++) { ar[b] = 0.f; ai[b] = 0.f; }
    #pragma unroll
    for (int k = 0; k < KSL; k++) {
        float wr = w1r[(size_t)k * HID + h];
        float wi = w1i[(size_t)k * HID + h];
        #pragma unroll
        for (int b = 0; b < BATCH; b++) {
            float xr = sxr[b][k], xi = sxi[b][k];
            ar[b] = fmaf(xr, wr, fmaf(-xi, wi, ar[b]));
            ai[b] = fmaf(xi, wr, fmaf( xr, wi, ai[b]));
        }
    }
    #pragma unroll
    for (int b = 0; b < BATCH; b++) {
        g_p1r[kz][b][h] = ar[b];
        g_p1i[kz][b][h] = ai[b];
    }
}

// ---------------- K3: mlp2 partials + fused gating tail (last block) -------
// grid (KS2=32), 256 threads. Stage 1: build o1[h0..h0+32) for 8 batches.
// Stage 2: each thread one f, 32-h slice, 8 batches. Last block to finish
// reduces all partials (fixed order), computes amp/logits/top-5, writes
// gates_out + g_mask, resets the ticket counter.
__global__ void __launch_bounds__(256)
mlp2_gate_kernel(const float* __restrict__ w2, const float* __restrict__ b1,
                 const float* __restrict__ b2, const float* __restrict__ w_gate,
                 float* __restrict__ gates_out) {
    const int hz = blockIdx.x;
    const int HS = HID / KS2;                        // 32
    const int h0 = hz * HS;
    __shared__ float s1r[BATCH][HS], s1i[BATCH][HS];
    {
        int b = threadIdx.x >> 5, hl = threadIdx.x & 31;   // exactly 256 = 8*32
        int h = h0 + hl;
        float ar = 0.f, ai = 0.f;
        #pragma unroll
        for (int kz = 0; kz < KS1; kz++) {
            ar += g_p1r[kz][b][h];
            ai += g_p1i[kz][b][h];
        }
        ar += b1[h]; ai += b1[HID + h];
        s1r[b][hl] = fmaxf(ar, 0.f);
        s1i[b][hl] = fmaxf(ai, 0.f);
    }
    __syncthreads();
    const int f = threadIdx.x;
    const float* w2r = w2 + (size_t)h0 * FDIM;
    const float* w2i = w2 + (size_t)(HID + h0) * FDIM;
    float ar[BATCH], ai[BATCH];
    #pragma unroll
    for (int b = 0; b < BATCH; b++) { ar[b] = 0.f; ai[b] = 0.f; }
    #pragma unroll
    for (int h = 0; h < HS; h++) {
        float wr = w2r[(size_t)h * FDIM + f];
        float wi = w2i[(size_t)h * FDIM + f];
        #pragma unroll
        for (int b = 0; b < BATCH; b++) {
            float xr = s1r[b][h], xi = s1i[b][h];
            ar[b] = fmaf(xr, wr, fmaf(-xi, wi, ar[b]));
            ai[b] = fmaf(xi, wr, fmaf( xr, wi, ai[b]));
        }
    }
    #pragma unroll
    for (int b = 0; b < BATCH; b++) {
        g_p2r[hz][b][f] = ar[b];
        g_p2i[hz][b][f] = ai[b];
    }

    // ---- last-block gating tail ----
    __threadfence();
    __shared__ unsigned int s_last;
    if (threadIdx.x == 0)
        s_last = (atomicAdd(&g_ctr, 1u) == KS2 - 1) ? 1u : 0u;
    __syncthreads();
    if (!s_last) return;

    __shared__ float samp[FDIM];
    __shared__ float slog[NEXP];
    const int t = threadIdx.x;
    for (int b = 0; b < BATCH; b++) {
        // fixed-order reduce + softshrink + amplitude
        float rr = 0.f, ii = 0.f;
        #pragma unroll
        for (int hz2 = 0; hz2 < KS2; hz2++) {
            rr += g_p2r[hz2][b][t];
            ii += g_p2i[hz2][b][t];
        }
        rr += b2[t]; ii += b2[FDIM + t];
        rr = (rr > 0.01f) ? rr - 0.01f : ((rr < -0.01f) ? rr + 0.01f : 0.f);
        ii = (ii > 0.01f) ? ii - 0.01f : ((ii < -0.01f) ? ii + 0.01f : 0.f);
        samp[t] = sqrtf(fmaf(rr, rr, fmaf(ii, ii, 1e-12f)));
        __syncthreads();
        // logits: 64 groups of 4 threads; all threads run the shfl
        int g = t >> 2, lg = t & 3;
        float acc = 0.f;
        if (g < NEXP) {
            #pragma unroll
            for (int i = 0; i < 64; i++) {
                int k = lg + i * 4;
                acc = fmaf(samp[k], w_gate[k * NEXP + g], acc);
            }
        }
        acc += __shfl_down_sync(0xffffffffu, acc, 2, 4);
        acc += __shfl_down_sync(0xffffffffu, acc, 1, 4);
        if (lg == 0 && g < NEXP) slog[g] = acc;
        __syncthreads();
        if (t == 0) {
            float v[NEXP];
            for (int e = 0; e < NEXP; e++) v[e] = slog[e];
            int   idx[TOPK];
            float val[TOPK];
            for (int tt = 0; tt < TOPK; tt++) {
                int bi = 0; float bv = v[0];
                for (int e = 1; e < NEXP; e++) if (v[e] > bv) { bv = v[e]; bi = e; }
                idx[tt] = bi; val[tt] = bv; v[bi] = -3.4e38f;
            }
            float mx = val[0], sum = 0.f, ex[TOPK];
            for (int tt = 0; tt < TOPK; tt++) { ex[tt] = expf(val[tt] - mx); sum += ex[tt]; }
            for (int e = 0; e < NEXP; e++) { gates_out[b * NEXP + e] = 0.f; g_mask[b][e] = 0.f; }
            for (int tt = 0; tt < TOPK; tt++) {
                gates_out[b * NEXP + idx[tt]] = ex[tt] / sum;
                g_mask[b][idx[tt]] = 1.0f;
            }
        }
        __syncthreads();   // protect samp/slog before next batch iteration
    }
    if (t == 0) g_ctr = 0;                            // reset for next replay
}

// ---------------- K5: main patch-embedding / zero-fill ----------------
// grid (1657, 8, 2): x = patch-row (reversed: big p first), y = batch,
// z = d-half (0 -> d in [0,256), 1 -> d in [256,512)). 256 threads, 1 d-col each.
__global__ void __launch_bounds__(256)
embed_kernel(const float* __restrict__ x, const float* __restrict__ Wv,
             float* __restrict__ out) {
    const int r = (TOTROWS - 1) - blockIdx.x;     // largest p scheduled first
    const int b = blockIdx.y;
    const int z = blockIdx.z;
    const int tid = threadIdx.x;

    // expert lookup (constant-mem scan, uniform)
    int e = 0;
    while (c_OFF[e + 1] <= r) e++;
    const int p = c_P[e];
    const int j = r - c_OFF[e];

    const size_t cstride = (size_t)TOTROWS * DMODEL;
    float* outbase = out + ((size_t)(b * NFEAT) * TOTROWS + r) * DMODEL + z * 256;

    if (g_mask[b][e] == 0.f) {
        // zero-fill 16 rows x 256 cols, float4
        float4 zz = make_float4(0.f, 0.f, 0.f, 0.f);
        #pragma unroll
        for (int idx = tid; idx < NFEAT * 64; idx += 256) {
            int c = idx >> 6, v = idx & 63;
            *(float4*)(outbase + (size_t)c * cstride + v * 4) = zz;
        }
        return;
    }

    extern __shared__ float xsm[];                // p*16 floats (<=32KB)
    {
        const float4* x4 = (const float4*)x;
        float4* xsm4 = (float4*)xsm;
        for (int idx = tid; idx < p * 4; idx += 256) {
            int q = idx >> 2, v = idx & 3;
            int l = j * p + q; if (l > SEQL - 1) l = SEQL - 1;   // edge pad
            xsm4[idx] = x4[(((size_t)b * SEQL + l) << 2) + v];
        }
    }
    __syncthreads();

    float acc[NFEAT];
    #pragma unroll
    for (int c = 0; c < NFEAT; c++) acc[c] = 0.f;

    const float* wv = Wv + (size_t)e * SEQL * DMODEL + z * 256 + tid;
    for (int q = 0; q < p; q++) {
        float w = wv[(size_t)q * DMODEL];
        const float* xq = xsm + q * NFEAT;
        #pragma unroll
        for (int c = 0; c < NFEAT; c++) acc[c] = fmaf(xq[c], w, acc[c]);
    }

    if (z == 0) {
        #pragma unroll
        for (int c = 0; c < NFEAT; c++)
            outbase[(size_t)c * cstride + tid] = acc[c] + g_feat[c][tid];
    } else {
        float pe = g_pos[j][tid];
        #pragma unroll
        for (int c = 0; c < NFEAT; c++)
            outbase[(size_t)c * cstride + tid] = acc[c] + pe;
    }
}

// ---------------- launch ----------------
extern "C" void kernel_launch(void* const* d_in, const int* in_sizes, int n_in,
                              void* d_out, int out_size) {
    const float* x       = (const float*)d_in[0];
    const float* w_start = (const float*)d_in[1];
    const float* b_start = (const float*)d_in[2];
    const float* w1      = (const float*)d_in[3];
    const float* b1      = (const float*)d_in[4];
    const float* w2      = (const float*)d_in[5];
    const float* b2      = (const float*)d_in[6];
    const float* w_gate  = (const float*)d_in[7];
    const float* Wv      = (const float*)d_in[8];
    float* out = (float*)d_out;
    float* gates_out = out + EMB_ELEMS;

    gate1_pos_kernel<<<8 + 136, 512>>>(x, w_start, b_start);
    mlp1_part_kernel<<<dim3(HID / 256, KS1), 256>>>(w1);
    mlp2_gate_kernel<<<KS2, 256>>>(w2, b1, b2, w_gate, gates_out);
    embed_kernel<<<dim3(TOTROWS, BATCH, 2), 256, 32768>>>(x, Wv, out);
}

// round 9
// speedup vs baseline: 1.2453x; 1.2453x over previous
#include <cuda_runtime.h>
#include <math.h>

// ---------------- problem constants ----------------
#define BATCH 8
#define SEQL 512
#define NFEAT 16
#define DMODEL 512
#define FDIM 256          // L/2
#define HID 1024          // 4*F
#define NEXP 43
#define TOPK 5
#define TOTROWS 1657
#define EMB_ELEMS 108593152LL   // 8*16*1657*512
#define KS1 16            // k-split for mlp1 (256/16 = 16 per block)
#define KS2 32            // h-split for mlp2 (1024/32 = 32 per block)

__constant__ int c_P[NEXP] = {
  2,3,4,5,6,7,8,9,10,11,12,13,14,15,16,17,18,19,20,21,22,23,24,25,26,
  28,30,32,34,36,39,42,46,51,56,64,73,85,102,128,170,256,512};
__constant__ int c_OFF[NEXP+1] = {
  0,256,427,555,658,744,818,882,939,991,1038,1081,1121,1158,1193,1225,
  1256,1285,1312,1338,1363,1387,1410,1432,1453,1473,1492,1510,1526,1542,
  1557,1571,1584,1596,1607,1617,1625,1633,1640,1646,1650,1654,1656,1657};

// ---------------- device scratch ----------------
__device__ float g_xr[BATCH][FDIM];
__device__ float g_xi[BATCH][FDIM];
__device__ float g_p1r[KS1][BATCH][HID];    // mlp1 partials
__device__ float g_p1i[KS1][BATCH][HID];
__device__ float g_p2r[KS2][BATCH][FDIM];   // mlp2 partials
__device__ float g_p2i[KS2][BATCH][FDIM];
__device__ float g_mask[BATCH][NEXP];
__device__ float g_feat[NFEAT][256];   // first half of d_model, depends on c
__device__ float g_pos[256][256];      // second half, depends on patch idx j

// ---------------- K1: gate1 (blocks 0-7) + pos tables (blocks 8-143) -------
__global__ void __launch_bounds__(512)
gate1_pos_kernel(const float* __restrict__ x,
                 const float* __restrict__ w_start,
                 const float* __restrict__ b_start) {
    if (blockIdx.x >= 8) {
        // positional tables in fp32 (abs err ~1e-4 << 1e-3 threshold)
        int idx = (blockIdx.x - 8) * 512 + threadIdx.x;   // 0 .. 69631
        const float L2_10000 = 13.287712379549449f;       // log2(10000)
        if (idx < NFEAT * 256) {
            int c = idx >> 8, i = idx & 255;
            float e2 = (float)(2 * (i >> 1)) * (1.0f / 256.0f);
            float inv = exp2f(-e2 * L2_10000);            // 1/10000^e2
            float a = (float)c * inv;
            g_feat[c][i] = (i & 1) ? cosf(a) : sinf(a);
        } else {
            int k2 = idx - NFEAT * 256;
            int j = k2 >> 8, i = k2 & 255;
            float e2 = (float)(2 * (i >> 1)) * (1.0f / 256.0f);
            float inv = exp2f(-e2 * L2_10000);
            float a = (float)j * inv;
            g_pos[j][i] = (i & 1) ? cosf(a) : sinf(a);
        }
        return;
    }
    // ---- gate1: start_fc + direct rFFT (ortho, drop DC), 512 threads ----
    __shared__ float xs[SEQL];
    __shared__ float2 tw[SEQL];
    __shared__ float2 ps[SEQL];
    __shared__ float ws[NFEAT];
    int b = blockIdx.x, t = threadIdx.x;
    if (t < NFEAT) ws[t] = w_start[t];
    {
        float s, c;
        sincospif((float)t * (1.0f / 256.0f), &s, &c);  // angle = 2*pi*t/512
        tw[t] = make_float2(c, s);
    }
    __syncthreads();
    {
        const float* xp = x + (((size_t)b * SEQL + t) << 4);
        float s = b_start[0];
        #pragma unroll
        for (int c = 0; c < NFEAT; c++) s = fmaf(xp[c], ws[c], s);
        xs[t] = s;
    }
    __syncthreads();
    int k  = (t & 255) + 1;                          // k = 1..256 (DC dropped)
    int l0 = (t >> 8) << 8;                          // 0 or 256
    float re = 0.f, im = 0.f;
    int m = (k * l0) & 511;
    #pragma unroll 8
    for (int i = 0; i < 256; i++) {
        float xv = xs[l0 + i];
        float2 w = tw[m];
        re = fmaf(xv,  w.x, re);
        im = fmaf(xv, -w.y, im);
        m = (m + k) & 511;
    }
    ps[t] = make_float2(re, im);
    __syncthreads();
    if (t < 256) {
        const float sc = 0.04419417382415922f;       // 1/sqrt(512)
        float2 lo = ps[t], hi = ps[t + 256];
        g_xr[b][t] = (lo.x + hi.x) * sc;
        g_xi[b][t] = (lo.y + hi.y) * sc;
    }
}

// ---------------- K2: complex layer 1 partials (all batches per thread) ----
// grid (HID/256=4, KS1=16), 256 threads. Each thread: one h, 16-k slice, 8 b.
__global__ void __launch_bounds__(256)
mlp1_part_kernel(const float* __restrict__ w1) {
    const int kz = blockIdx.y;
    const int h  = blockIdx.x * 256 + threadIdx.x;   // 0..1023
    const int KSL = FDIM / KS1;                      // 16
    const int k0 = kz * KSL;
    __shared__ float sxr[BATCH][KSL], sxi[BATCH][KSL];
    if (threadIdx.x < BATCH * KSL) {
        int b = threadIdx.x >> 4, k = threadIdx.x & 15;
        sxr[b][k] = g_xr[b][k0 + k];
        sxi[b][k] = g_xi[b][k0 + k];
    }
    __syncthreads();
    const float* w1r = w1 + (size_t)k0 * HID;
    const float* w1i = w1 + (size_t)(FDIM + k0) * HID;
    float ar[BATCH], ai[BATCH];
    #pragma unroll
    for (int b = 0; b < BATCH; b++) { ar[b] = 0.f; ai[b] = 0.f; }
    #pragma unroll
    for (int k = 0; k < KSL; k++) {
        float wr = w1r[(size_t)k * HID + h];
        float wi = w1i[(size_t)k * HID + h];
        #pragma unroll
        for (int b = 0; b < BATCH; b++) {
            float xr = sxr[b][k], xi = sxi[b][k];
            ar[b] = fmaf(xr, wr, fmaf(-xi, wi, ar[b]));
            ai[b] = fmaf(xi, wr, fmaf( xr, wi, ai[b]));
        }
    }
    #pragma unroll
    for (int b = 0; b < BATCH; b++) {
        g_p1r[kz][b][h] = ar[b];
        g_p1i[kz][b][h] = ai[b];
    }
}

// ---------------- K3: reduce o1 slice + complex layer 2 partials -----------
// grid (KS2=32), 256 threads. Stage 1: build o1[h0..h0+32) for 8 batches.
// Stage 2: each thread one f, 32-h slice, 8 batches.
__global__ void __launch_bounds__(256)
mlp2_part_kernel(const float* __restrict__ w2, const float* __restrict__ b1) {
    const int hz = blockIdx.x;
    const int HS = HID / KS2;                        // 32
    const int h0 = hz * HS;
    __shared__ float s1r[BATCH][HS], s1i[BATCH][HS];
    {
        int b = threadIdx.x >> 5, hl = threadIdx.x & 31;   // exactly 256 = 8*32
        int h = h0 + hl;
        float ar = 0.f, ai = 0.f;
        #pragma unroll
        for (int kz = 0; kz < KS1; kz++) {
            ar += g_p1r[kz][b][h];
            ai += g_p1i[kz][b][h];
        }
        ar += b1[h]; ai += b1[HID + h];
        s1r[b][hl] = fmaxf(ar, 0.f);
        s1i[b][hl] = fmaxf(ai, 0.f);
    }
    __syncthreads();
    const int f = threadIdx.x;
    const float* w2r = w2 + (size_t)h0 * FDIM;
    const float* w2i = w2 + (size_t)(HID + h0) * FDIM;
    float ar[BATCH], ai[BATCH];
    #pragma unroll
    for (int b = 0; b < BATCH; b++) { ar[b] = 0.f; ai[b] = 0.f; }
    #pragma unroll
    for (int h = 0; h < HS; h++) {
        float wr = w2r[(size_t)h * FDIM + f];
        float wi = w2i[(size_t)h * FDIM + f];
        #pragma unroll
        for (int b = 0; b < BATCH; b++) {
            float xr = s1r[b][h], xi = s1i[b][h];
            ar[b] = fmaf(xr, wr, fmaf(-xi, wi, ar[b]));
            ai[b] = fmaf(xi, wr, fmaf( xr, wi, ai[b]));
        }
    }
    #pragma unroll
    for (int b = 0; b < BATCH; b++) {
        g_p2r[hz][b][f] = ar[b];
        g_p2i[hz][b][f] = ai[b];
    }
}

// ---------------- K4: reduce + softshrink + amp + logits + top-5 ----------
// grid (BATCH), 512 threads. 8-thread group per expert for logits.
__global__ void __launch_bounds__(512)
gate2_kernel(const float* __restrict__ b2, const float* __restrict__ w_gate,
             float* __restrict__ gates_out) {
    int b = blockIdx.x, t = threadIdx.x;
    __shared__ float samp[FDIM];
    __shared__ float slog[NEXP];
    if (t < FDIM) {
        int f = t;
        float ar = 0.f, ai = 0.f;
        #pragma unroll
        for (int hz = 0; hz < KS2; hz++) {
            ar += g_p2r[hz][b][f];
            ai += g_p2i[hz][b][f];
        }
        ar += b2[f]; ai += b2[FDIM + f];
        ar = (ar > 0.01f) ? ar - 0.01f : ((ar < -0.01f) ? ar + 0.01f : 0.f);
        ai = (ai > 0.01f) ? ai - 0.01f : ((ai < -0.01f) ? ai + 0.01f : 0.f);
        samp[f] = sqrtf(fmaf(ar, ar, fmaf(ai, ai, 1e-12f)));
    }
    __syncthreads();
    // logits: 64 groups of 8 threads; ALL threads run the shfl (full-warp
    // convergence), groups >= NEXP compute zeros and discard.
    int g = t >> 3, lg = t & 7;
    float acc = 0.f;
    if (g < NEXP) {
        #pragma unroll
        for (int i = 0; i < 32; i++) {
            int k = lg + i * 8;
            acc = fmaf(samp[k], w_gate[k * NEXP + g], acc);
        }
    }
    acc += __shfl_down_sync(0xffffffffu, acc, 4, 8);
    acc += __shfl_down_sync(0xffffffffu, acc, 2, 8);
    acc += __shfl_down_sync(0xffffffffu, acc, 1, 8);
    if (lg == 0 && g < NEXP) slog[g] = acc;
    __syncthreads();
    if (t == 0) {
        float v[NEXP];
        for (int e = 0; e < NEXP; e++) v[e] = slog[e];
        int   idx[TOPK];
        float val[TOPK];
        for (int tt = 0; tt < TOPK; tt++) {
            int bi = 0; float bv = v[0];
            for (int e = 1; e < NEXP; e++) if (v[e] > bv) { bv = v[e]; bi = e; }
            idx[tt] = bi; val[tt] = bv; v[bi] = -3.4e38f;
        }
        float mx = val[0], sum = 0.f, ex[TOPK];
        for (int tt = 0; tt < TOPK; tt++) { ex[tt] = expf(val[tt] - mx); sum += ex[tt]; }
        for (int e = 0; e < NEXP; e++) { gates_out[b * NEXP + e] = 0.f; g_mask[b][e] = 0.f; }
        for (int tt = 0; tt < TOPK; tt++) {
            gates_out[b * NEXP + idx[tt]] = ex[tt] / sum;
            g_mask[b][idx[tt]] = 1.0f;
        }
    }
}

// ---------------- K5: main patch-embedding / zero-fill ----------------
// grid (1657, 8): x = patch-row (reversed: big p first), y = batch.
// 256 threads; each thread owns 2 consecutive d-cols (full 512-d row/block).
__global__ void __launch_bounds__(256)
embed_kernel(const float* __restrict__ x, const float* __restrict__ Wv,
             float* __restrict__ out) {
    const int r = (TOTROWS - 1) - blockIdx.x;     // largest p scheduled first
    const int b = blockIdx.y;
    const int tid = threadIdx.x;
    const int d0 = tid * 2;                        // 0,2,...,510

    // expert lookup (constant-mem scan, uniform)
    int e = 0;
    while (c_OFF[e + 1] <= r) e++;
    const int p = c_P[e];
    const int j = r - c_OFF[e];

    const size_t cstride = (size_t)TOTROWS * DMODEL;
    float* outb = out + ((size_t)(b * NFEAT) * TOTROWS + r) * DMODEL;

    if (g_mask[b][e] == 0.f) {
        // zero-fill 16 rows x 512 cols, float4 (NFEAT*128 = 2048 vec4)
        float4 zz = make_float4(0.f, 0.f, 0.f, 0.f);
        #pragma unroll
        for (int idx = tid; idx < NFEAT * 128; idx += 256) {
            int c = idx >> 7, v = idx & 127;
            *(float4*)(outb + (size_t)c * cstride + v * 4) = zz;
        }
        return;
    }

    extern __shared__ float xsm[];                // p*16 floats (<=32KB)
    {
        const float4* x4 = (const float4*)x;
        float4* xsm4 = (float4*)xsm;
        for (int idx = tid; idx < p * 4; idx += 256) {
            int q = idx >> 2, v = idx & 3;
            int l = j * p + q; if (l > SEQL - 1) l = SEQL - 1;   // edge pad
            xsm4[idx] = x4[(((size_t)b * SEQL + l) << 2) + v];
        }
    }
    __syncthreads();

    float2 acc[NFEAT];
    #pragma unroll
    for (int c = 0; c < NFEAT; c++) acc[c] = make_float2(0.f, 0.f);

    const float* wv = Wv + (size_t)e * SEQL * DMODEL + d0;
    for (int q = 0; q < p; q++) {
        float2 w = *(const float2*)(wv + (size_t)q * DMODEL);
        const float4* xq4 = (const float4*)(xsm + q * NFEAT);
        float xv[NFEAT];
        *(float4*)(xv +  0) = xq4[0];
        *(float4*)(xv +  4) = xq4[1];
        *(float4*)(xv +  8) = xq4[2];
        *(float4*)(xv + 12) = xq4[3];
        #pragma unroll
        for (int c = 0; c < NFEAT; c++) {
            acc[c].x = fmaf(xv[c], w.x, acc[c].x);
            acc[c].y = fmaf(xv[c], w.y, acc[c].y);
        }
    }

    if (d0 < 256) {
        #pragma unroll
        for (int c = 0; c < NFEAT; c++) {
            float2 o = make_float2(acc[c].x + g_feat[c][d0],
                                   acc[c].y + g_feat[c][d0 + 1]);
            *(float2*)(outb + (size_t)c * cstride + d0) = o;
        }
    } else {
        float pe0 = g_pos[j][d0 - 256], pe1 = g_pos[j][d0 - 255];
        #pragma unroll
        for (int c = 0; c < NFEAT; c++) {
            float2 o = make_float2(acc[c].x + pe0, acc[c].y + pe1);
            *(float2*)(outb + (size_t)c * cstride + d0) = o;
        }
    }
}

// ---------------- launch ----------------
extern "C" void kernel_launch(void* const* d_in, const int* in_sizes, int n_in,
                              void* d_out, int out_size) {
    const float* x       = (const float*)d_in[0];
    const float* w_start = (const float*)d_in[1];
    const float* b_start = (const float*)d_in[2];
    const float* w1      = (const float*)d_in[3];
    const float* b1      = (const float*)d_in[4];
    const float* w2      = (const float*)d_in[5];
    const float* b2      = (const float*)d_in[6];
    const float* w_gate  = (const float*)d_in[7];
    const float* Wv      = (const float*)d_in[8];
    float* out = (float*)d_out;
    float* gates_out = out + EMB_ELEMS;

    gate1_pos_kernel<<<8 + 136, 512>>>(x, w_start, b_start);
    mlp1_part_kernel<<<dim3(HID / 256, KS1), 256>>>(w1);
    mlp2_part_kernel<<<KS2, 256>>>(w2, b1);
    gate2_kernel<<<BATCH, 512>>>(b2, w_gate, gates_out);
    embed_kernel<<<dim3(TOTROWS, BATCH), 256, 32768>>>(x, Wv, out);
}

// round 10
// speedup vs baseline: 1.2501x; 1.0039x over previous
#include <cuda_runtime.h>
#include <math.h>

// ---------------- problem constants ----------------
#define BATCH 8
#define SEQL 512
#define NFEAT 16
#define DMODEL 512
#define FDIM 256          // L/2
#define HID 1024          // 4*F
#define NEXP 43
#define TOPK 5
#define TOTROWS 1657
#define EMB_ELEMS 108593152LL   // 8*16*1657*512
#define KS1 16            // k-split for mlp1 (256/16 = 16 per block)
#define KS2 32            // h-split for mlp2 (1024/32 = 32 per block)

__constant__ int c_P[NEXP] = {
  2,3,4,5,6,7,8,9,10,11,12,13,14,15,16,17,18,19,20,21,22,23,24,25,26,
  28,30,32,34,36,39,42,46,51,56,64,73,85,102,128,170,256,512};
__constant__ int c_OFF[NEXP+1] = {
  0,256,427,555,658,744,818,882,939,991,1038,1081,1121,1158,1193,1225,
  1256,1285,1312,1338,1363,1387,1410,1432,1453,1473,1492,1510,1526,1542,
  1557,1571,1584,1596,1607,1617,1625,1633,1640,1646,1650,1654,1656,1657};

// ---------------- device scratch ----------------
__device__ float g_xr[BATCH][FDIM];
__device__ float g_xi[BATCH][FDIM];
__device__ float g_p1r[KS1][BATCH][HID];    // mlp1 partials
__device__ float g_p1i[KS1][BATCH][HID];
__device__ float g_p2r[KS2][BATCH][FDIM];   // mlp2 partials
__device__ float g_p2i[KS2][BATCH][FDIM];
__device__ float g_mask[BATCH][NEXP];
__device__ float g_feat[NFEAT][256];   // first half of d_model, depends on c
__device__ float g_pos[256][256];      // second half, depends on patch idx j

// ---------------- K1: gate1 (blocks 0-7) + pos tables (blocks 8-143) -------
__global__ void __launch_bounds__(512)
gate1_pos_kernel(const float* __restrict__ x,
                 const float* __restrict__ w_start,
                 const float* __restrict__ b_start) {
    if (blockIdx.x >= 8) {
        // positional tables in fp32 (abs err ~1e-4 << 1e-3 threshold)
        int idx = (blockIdx.x - 8) * 512 + threadIdx.x;   // 0 .. 69631
        const float L2_10000 = 13.287712379549449f;       // log2(10000)
        if (idx < NFEAT * 256) {
            int c = idx >> 8, i = idx & 255;
            float e2 = (float)(2 * (i >> 1)) * (1.0f / 256.0f);
            float inv = exp2f(-e2 * L2_10000);            // 1/10000^e2
            float a = (float)c * inv;
            g_feat[c][i] = (i & 1) ? cosf(a) : sinf(a);
        } else {
            int k2 = idx - NFEAT * 256;
            int j = k2 >> 8, i = k2 & 255;
            float e2 = (float)(2 * (i >> 1)) * (1.0f / 256.0f);
            float inv = exp2f(-e2 * L2_10000);
            float a = (float)j * inv;
            g_pos[j][i] = (i & 1) ? cosf(a) : sinf(a);
        }
        return;
    }
    // ---- gate1: start_fc + direct rFFT (ortho, drop DC), 512 threads ----
    __shared__ float xs[SEQL];
    __shared__ float2 tw[SEQL];
    __shared__ float2 ps[SEQL];
    __shared__ float ws[NFEAT];
    int b = blockIdx.x, t = threadIdx.x;
    if (t < NFEAT) ws[t] = w_start[t];
    {
        float s, c;
        sincospif((float)t * (1.0f / 256.0f), &s, &c);  // angle = 2*pi*t/512
        tw[t] = make_float2(c, s);
    }
    __syncthreads();
    {
        const float* xp = x + (((size_t)b * SEQL + t) << 4);
        float s = b_start[0];
        #pragma unroll
        for (int c = 0; c < NFEAT; c++) s = fmaf(xp[c], ws[c], s);
        xs[t] = s;
    }
    __syncthreads();
    int k  = (t & 255) + 1;                          // k = 1..256 (DC dropped)
    int l0 = (t >> 8) << 8;                          // 0 or 256
    float re = 0.f, im = 0.f;
    int m = (k * l0) & 511;
    #pragma unroll 8
    for (int i = 0; i < 256; i++) {
        float xv = xs[l0 + i];
        float2 w = tw[m];
        re = fmaf(xv,  w.x, re);
        im = fmaf(xv, -w.y, im);
        m = (m + k) & 511;
    }
    ps[t] = make_float2(re, im);
    __syncthreads();
    if (t < 256) {
        const float sc = 0.04419417382415922f;       // 1/sqrt(512)
        float2 lo = ps[t], hi = ps[t + 256];
        g_xr[b][t] = (lo.x + hi.x) * sc;
        g_xi[b][t] = (lo.y + hi.y) * sc;
    }
}

// ---------------- K2: complex layer 1 partials (all batches per thread) ----
// grid (HID/256=4, KS1=16), 256 threads. Each thread: one h, 16-k slice, 8 b.
__global__ void __launch_bounds__(256)
mlp1_part_kernel(const float* __restrict__ w1) {
    const int kz = blockIdx.y;
    const int h  = blockIdx.x * 256 + threadIdx.x;   // 0..1023
    const int KSL = FDIM / KS1;                      // 16
    const int k0 = kz * KSL;
    __shared__ float sxr[BATCH][KSL], sxi[BATCH][KSL];
    if (threadIdx.x < BATCH * KSL) {
        int b = threadIdx.x >> 4, k = threadIdx.x & 15;
        sxr[b][k] = g_xr[b][k0 + k];
        sxi[b][k] = g_xi[b][k0 + k];
    }
    __syncthreads();
    const float* w1r = w1 + (size_t)k0 * HID;
    const float* w1i = w1 + (size_t)(FDIM + k0) * HID;
    float ar[BATCH], ai[BATCH];
    #pragma unroll
    for (int b = 0; b < BATCH; b++) { ar[b] = 0.f; ai[b] = 0.f; }
    #pragma unroll
    for (int k = 0; k < KSL; k++) {
        float wr = w1r[(size_t)k * HID + h];
        float wi = w1i[(size_t)k * HID + h];
        #pragma unroll
        for (int b = 0; b < BATCH; b++) {
            float xr = sxr[b][k], xi = sxi[b][k];
            ar[b] = fmaf(xr, wr, fmaf(-xi, wi, ar[b]));
            ai[b] = fmaf(xi, wr, fmaf( xr, wi, ai[b]));
        }
    }
    #pragma unroll
    for (int b = 0; b < BATCH; b++) {
        g_p1r[kz][b][h] = ar[b];
        g_p1i[kz][b][h] = ai[b];
    }
}

// ---------------- K3: reduce o1 slice + complex layer 2 partials -----------
// grid (KS2=32), 256 threads. Stage 1: build o1[h0..h0+32) for 8 batches.
// Stage 2: each thread one f, 32-h slice, 8 batches.
__global__ void __launch_bounds__(256)
mlp2_part_kernel(const float* __restrict__ w2, const float* __restrict__ b1) {
    const int hz = blockIdx.x;
    const int HS = HID / KS2;                        // 32
    const int h0 = hz * HS;
    __shared__ float s1r[BATCH][HS], s1i[BATCH][HS];
    {
        int b = threadIdx.x >> 5, hl = threadIdx.x & 31;   // exactly 256 = 8*32
        int h = h0 + hl;
        float ar = 0.f, ai = 0.f;
        #pragma unroll
        for (int kz = 0; kz < KS1; kz++) {
            ar += g_p1r[kz][b][h];
            ai += g_p1i[kz][b][h];
        }
        ar += b1[h]; ai += b1[HID + h];
        s1r[b][hl] = fmaxf(ar, 0.f);
        s1i[b][hl] = fmaxf(ai, 0.f);
    }
    __syncthreads();
    const int f = threadIdx.x;
    const float* w2r = w2 + (size_t)h0 * FDIM;
    const float* w2i = w2 + (size_t)(HID + h0) * FDIM;
    float ar[BATCH], ai[BATCH];
    #pragma unroll
    for (int b = 0; b < BATCH; b++) { ar[b] = 0.f; ai[b] = 0.f; }
    #pragma unroll
    for (int h = 0; h < HS; h++) {
        float wr = w2r[(size_t)h * FDIM + f];
        float wi = w2i[(size_t)h * FDIM + f];
        #pragma unroll
        for (int b = 0; b < BATCH; b++) {
            float xr = s1r[b][h], xi = s1i[b][h];
            ar[b] = fmaf(xr, wr, fmaf(-xi, wi, ar[b]));
            ai[b] = fmaf(xi, wr, fmaf( xr, wi, ai[b]));
        }
    }
    #pragma unroll
    for (int b = 0; b < BATCH; b++) {
        g_p2r[hz][b][f] = ar[b];
        g_p2i[hz][b][f] = ai[b];
    }
}

// ---------------- K4: reduce + softshrink + amp + logits + top-5 ----------
// grid (BATCH), 512 threads. 8-thread group per expert for logits.
__global__ void __launch_bounds__(512)
gate2_kernel(const float* __restrict__ b2, const float* __restrict__ w_gate,
             float* __restrict__ gates_out) {
    int b = blockIdx.x, t = threadIdx.x;
    __shared__ float samp[FDIM];
    __shared__ float slog[NEXP];
    if (t < FDIM) {
        int f = t;
        float ar = 0.f, ai = 0.f;
        #pragma unroll
        for (int hz = 0; hz < KS2; hz++) {
            ar += g_p2r[hz][b][f];
            ai += g_p2i[hz][b][f];
        }
        ar += b2[f]; ai += b2[FDIM + f];
        ar = (ar > 0.01f) ? ar - 0.01f : ((ar < -0.01f) ? ar + 0.01f : 0.f);
        ai = (ai > 0.01f) ? ai - 0.01f : ((ai < -0.01f) ? ai + 0.01f : 0.f);
        samp[f] = sqrtf(fmaf(ar, ar, fmaf(ai, ai, 1e-12f)));
    }
    __syncthreads();
    // logits: 64 groups of 8 threads; ALL threads run the shfl (full-warp
    // convergence), groups >= NEXP compute zeros and discard.
    int g = t >> 3, lg = t & 7;
    float acc = 0.f;
    if (g < NEXP) {
        #pragma unroll
        for (int i = 0; i < 32; i++) {
            int k = lg + i * 8;
            acc = fmaf(samp[k], w_gate[k * NEXP + g], acc);
        }
    }
    acc += __shfl_down_sync(0xffffffffu, acc, 4, 8);
    acc += __shfl_down_sync(0xffffffffu, acc, 2, 8);
    acc += __shfl_down_sync(0xffffffffu, acc, 1, 8);
    if (lg == 0 && g < NEXP) slog[g] = acc;
    __syncthreads();
    if (t == 0) {
        float v[NEXP];
        for (int e = 0; e < NEXP; e++) v[e] = slog[e];
        int   idx[TOPK];
        float val[TOPK];
        for (int tt = 0; tt < TOPK; tt++) {
            int bi = 0; float bv = v[0];
            for (int e = 1; e < NEXP; e++) if (v[e] > bv) { bv = v[e]; bi = e; }
            idx[tt] = bi; val[tt] = bv; v[bi] = -3.4e38f;
        }
        float mx = val[0], sum = 0.f, ex[TOPK];
        for (int tt = 0; tt < TOPK; tt++) { ex[tt] = expf(val[tt] - mx); sum += ex[tt]; }
        for (int e = 0; e < NEXP; e++) { gates_out[b * NEXP + e] = 0.f; g_mask[b][e] = 0.f; }
        for (int tt = 0; tt < TOPK; tt++) {
            gates_out[b * NEXP + idx[tt]] = ex[tt] / sum;
            g_mask[b][idx[tt]] = 1.0f;
        }
    }
}

// ---------------- K5: main patch-embedding / zero-fill ----------------
// grid (1657, 8): x = patch-row (reversed: big p first), y = batch.
// 128 threads; each thread owns 4 consecutive d-cols (full 512-d row/block).
__global__ void __launch_bounds__(128)
embed_kernel(const float* __restrict__ x, const float* __restrict__ Wv,
             float* __restrict__ out) {
    const int r = (TOTROWS - 1) - blockIdx.x;     // largest p scheduled first
    const int b = blockIdx.y;
    const int tid = threadIdx.x;
    const int d0 = tid * 4;                        // 0,4,...,508

    // expert lookup (constant-mem scan, uniform)
    int e = 0;
    while (c_OFF[e + 1] <= r) e++;
    const int p = c_P[e];
    const int j = r - c_OFF[e];

    const size_t cstride = (size_t)TOTROWS * DMODEL;
    float* outb = out + ((size_t)(b * NFEAT) * TOTROWS + r) * DMODEL;

    if (g_mask[b][e] == 0.f) {
        // zero-fill 16 rows x 512 cols, float4 (NFEAT*128 = 2048 vec4)
        float4 zz = make_float4(0.f, 0.f, 0.f, 0.f);
        #pragma unroll
        for (int idx = tid; idx < NFEAT * 128; idx += 128) {
            int c = idx >> 7, v = idx & 127;
            *(float4*)(outb + (size_t)c * cstride + v * 4) = zz;
        }
        return;
    }

    extern __shared__ float xsm[];                // p*16 floats (<=32KB)
    {
        const float4* x4 = (const float4*)x;
        float4* xsm4 = (float4*)xsm;
        for (int idx = tid; idx < p * 4; idx += 128) {
            int q = idx >> 2, v = idx & 3;
            int l = j * p + q; if (l > SEQL - 1) l = SEQL - 1;   // edge pad
            xsm4[idx] = x4[(((size_t)b * SEQL + l) << 2) + v];
        }
    }
    __syncthreads();

    float4 acc[NFEAT];
    #pragma unroll
    for (int c = 0; c < NFEAT; c++) acc[c] = make_float4(0.f, 0.f, 0.f, 0.f);

    const float* wv = Wv + (size_t)e * SEQL * DMODEL + d0;
    for (int q = 0; q < p; q++) {
        float4 w = *(const float4*)(wv + (size_t)q * DMODEL);
        const float4* xq4 = (const float4*)(xsm + q * NFEAT);
        float xv[NFEAT];
        *(float4*)(xv +  0) = xq4[0];
        *(float4*)(xv +  4) = xq4[1];
        *(float4*)(xv +  8) = xq4[2];
        *(float4*)(xv + 12) = xq4[3];
        #pragma unroll
        for (int c = 0; c < NFEAT; c++) {
            acc[c].x = fmaf(xv[c], w.x, acc[c].x);
            acc[c].y = fmaf(xv[c], w.y, acc[c].y);
            acc[c].z = fmaf(xv[c], w.z, acc[c].z);
            acc[c].w = fmaf(xv[c], w.w, acc[c].w);
        }
    }

    if (d0 < 256) {
        float4 pe = *(const float4*)&g_feat[0][d0];  // placeholder; per-c below
        #pragma unroll
        for (int c = 0; c < NFEAT; c++) {
            pe = *(const float4*)&g_feat[c][d0];
            float4 o = make_float4(acc[c].x + pe.x, acc[c].y + pe.y,
                                   acc[c].z + pe.z, acc[c].w + pe.w);
            *(float4*)(outb + (size_t)c * cstride + d0) = o;
        }
    } else {
        float4 pe = *(const float4*)&g_pos[j][d0 - 256];
        #pragma unroll
        for (int c = 0; c < NFEAT; c++) {
            float4 o = make_float4(acc[c].x + pe.x, acc[c].y + pe.y,
                                   acc[c].z + pe.z, acc[c].w + pe.w);
            *(float4*)(outb + (size_t)c * cstride + d0) = o;
        }
    }
}

// ---------------- launch ----------------
extern "C" void kernel_launch(void* const* d_in, const int* in_sizes, int n_in,
                              void* d_out, int out_size) {
    const float* x       = (const float*)d_in[0];
    const float* w_start = (const float*)d_in[1];
    const float* b_start = (const float*)d_in[2];
    const float* w1      = (const float*)d_in[3];
    const float* b1      = (const float*)d_in[4];
    const float* w2      = (const float*)d_in[5];
    const float* b2      = (const float*)d_in[6];
    const float* w_gate  = (const float*)d_in[7];
    const float* Wv      = (const float*)d_in[8];
    float* out = (float*)d_out;
    float* gates_out = out + EMB_ELEMS;

    gate1_pos_kernel<<<8 + 136, 512>>>(x, w_start, b_start);
    mlp1_part_kernel<<<dim3(HID / 256, KS1), 256>>>(w1);
    mlp2_part_kernel<<<KS2, 256>>>(w2, b1);
    gate2_kernel<<<BATCH, 512>>>(b2, w_gate, gates_out);
    embed_kernel<<<dim3(TOTROWS, BATCH), 128, 32768>>>(x, Wv, out);
}

// round 11
// speedup vs baseline: 1.3374x; 1.0698x over previous
#include <cuda_runtime.h>
#include <math.h>

// ---------------- problem constants ----------------
#define BATCH 8
#define SEQL 512
#define NFEAT 16
#define DMODEL 512
#define FDIM 256          // L/2
#define HID 1024          // 4*F
#define NEXP 43
#define TOPK 5
#define TOTROWS 1657
#define EMB_ELEMS 108593152LL   // 8*16*1657*512
#define KS1 16            // k-split for mlp1 (256/16 = 16 per block)
#define KS2 32            // h-split for mlp2 (1024/32 = 32 per block)

__constant__ int c_P[NEXP] = {
  2,3,4,5,6,7,8,9,10,11,12,13,14,15,16,17,18,19,20,21,22,23,24,25,26,
  28,30,32,34,36,39,42,46,51,56,64,73,85,102,128,170,256,512};
__constant__ int c_OFF[NEXP+1] = {
  0,256,427,555,658,744,818,882,939,991,1038,1081,1121,1158,1193,1225,
  1256,1285,1312,1338,1363,1387,1410,1432,1453,1473,1492,1510,1526,1542,
  1557,1571,1584,1596,1607,1617,1625,1633,1640,1646,1650,1654,1656,1657};

// ---------------- device scratch ----------------
__device__ float g_xr[BATCH][FDIM];
__device__ float g_xi[BATCH][FDIM];
__device__ float g_p1r[KS1][BATCH][HID];    // mlp1 partials
__device__ float g_p1i[KS1][BATCH][HID];
__device__ float g_p2r[KS2][BATCH][FDIM];   // mlp2 partials
__device__ float g_p2i[KS2][BATCH][FDIM];
__device__ float g_mask[BATCH][NEXP];
__device__ float g_feat[NFEAT][256];   // first half of d_model, depends on c
__device__ float g_pos[256][256];      // second half, depends on patch idx j

// ---------------- K1: gate1 (blocks 0-7) + pos tables (blocks 8-143) -------
__global__ void __launch_bounds__(512)
gate1_pos_kernel(const float* __restrict__ x,
                 const float* __restrict__ w_start,
                 const float* __restrict__ b_start) {
    cudaTriggerProgrammaticLaunchCompletion();   // release mlp1's prologue
    if (blockIdx.x >= 8) {
        // positional tables in fp32 (abs err ~1e-4 << 1e-3 threshold)
        int idx = (blockIdx.x - 8) * 512 + threadIdx.x;   // 0 .. 69631
        const float L2_10000 = 13.287712379549449f;       // log2(10000)
        if (idx < NFEAT * 256) {
            int c = idx >> 8, i = idx & 255;
            float e2 = (float)(2 * (i >> 1)) * (1.0f / 256.0f);
            float inv = exp2f(-e2 * L2_10000);            // 1/10000^e2
            float a = (float)c * inv;
            g_feat[c][i] = (i & 1) ? cosf(a) : sinf(a);
        } else {
            int k2 = idx - NFEAT * 256;
            int j = k2 >> 8, i = k2 & 255;
            float e2 = (float)(2 * (i >> 1)) * (1.0f / 256.0f);
            float inv = exp2f(-e2 * L2_10000);
            float a = (float)j * inv;
            g_pos[j][i] = (i & 1) ? cosf(a) : sinf(a);
        }
        return;
    }
    // ---- gate1: start_fc + direct rFFT (ortho, drop DC), 512 threads ----
    __shared__ float xs[SEQL];
    __shared__ float2 tw[SEQL];
    __shared__ float2 ps[SEQL];
    __shared__ float ws[NFEAT];
    int b = blockIdx.x, t = threadIdx.x;
    if (t < NFEAT) ws[t] = w_start[t];
    {
        float s, c;
        sincospif((float)t * (1.0f / 256.0f), &s, &c);  // angle = 2*pi*t/512
        tw[t] = make_float2(c, s);
    }
    __syncthreads();
    {
        const float* xp = x + (((size_t)b * SEQL + t) << 4);
        float s = b_start[0];
        #pragma unroll
        for (int c = 0; c < NFEAT; c++) s = fmaf(xp[c], ws[c], s);
        xs[t] = s;
    }
    __syncthreads();
    int k  = (t & 255) + 1;                          // k = 1..256 (DC dropped)
    int l0 = (t >> 8) << 8;                          // 0 or 256
    float re = 0.f, im = 0.f;
    int m = (k * l0) & 511;
    #pragma unroll 8
    for (int i = 0; i < 256; i++) {
        float xv = xs[l0 + i];
        float2 w = tw[m];
        re = fmaf(xv,  w.x, re);
        im = fmaf(xv, -w.y, im);
        m = (m + k) & 511;
    }
    ps[t] = make_float2(re, im);
    __syncthreads();
    if (t < 256) {
        const float sc = 0.04419417382415922f;       // 1/sqrt(512)
        float2 lo = ps[t], hi = ps[t + 256];
        g_xr[b][t] = (lo.x + hi.x) * sc;
        g_xi[b][t] = (lo.y + hi.y) * sc;
    }
}

// ---------------- K2: complex layer 1 partials (PDL: preload w1) ----------
// grid (HID/256=4, KS1=16), 256 threads. Each thread: one h, 16-k slice, 8 b.
__global__ void __launch_bounds__(256)
mlp1_part_kernel(const float* __restrict__ w1) {
    cudaTriggerProgrammaticLaunchCompletion();       // release mlp2's prologue
    const int kz = blockIdx.y;
    const int h  = blockIdx.x * 256 + threadIdx.x;   // 0..1023
    const int KSL = FDIM / KS1;                      // 16
    const int k0 = kz * KSL;
    // ---- prologue (independent of gate1): stream w1 slice into registers
    float wr[KSL], wi[KSL];
    {
        const float* w1r = w1 + (size_t)k0 * HID;
        const float* w1i = w1 + (size_t)(FDIM + k0) * HID;
        #pragma unroll
        for (int k = 0; k < KSL; k++) {
            wr[k] = w1r[(size_t)k * HID + h];
            wi[k] = w1i[(size_t)k * HID + h];
        }
    }
    cudaGridDependencySynchronize();                 // wait for gate1 results
    __shared__ float sxr[BATCH][KSL], sxi[BATCH][KSL];
    if (threadIdx.x < BATCH * KSL) {
        int b = threadIdx.x >> 4, k = threadIdx.x & 15;
        sxr[b][k] = g_xr[b][k0 + k];
        sxi[b][k] = g_xi[b][k0 + k];
    }
    __syncthreads();
    float ar[BATCH], ai[BATCH];
    #pragma unroll
    for (int b = 0; b < BATCH; b++) { ar[b] = 0.f; ai[b] = 0.f; }
    #pragma unroll
    for (int k = 0; k < KSL; k++) {
        #pragma unroll
        for (int b = 0; b < BATCH; b++) {
            float xr = sxr[b][k], xi = sxi[b][k];
            ar[b] = fmaf(xr, wr[k], fmaf(-xi, wi[k], ar[b]));
            ai[b] = fmaf(xi, wr[k], fmaf( xr, wi[k], ai[b]));
        }
    }
    #pragma unroll
    for (int b = 0; b < BATCH; b++) {
        g_p1r[kz][b][h] = ar[b];
        g_p1i[kz][b][h] = ai[b];
    }
}

// ---------------- K3: mlp2 partials (PDL: preload w2) ----------------------
// grid (KS2=32), 256 threads. Stage 1: build o1[h0..h0+32) for 8 batches.
// Stage 2: each thread one f, 32-h slice, 8 batches.
__global__ void __launch_bounds__(256)
mlp2_part_kernel(const float* __restrict__ w2, const float* __restrict__ b1) {
    cudaTriggerProgrammaticLaunchCompletion();       // release gate2's prologue
    const int hz = blockIdx.x;
    const int HS = HID / KS2;                        // 32
    const int h0 = hz * HS;
    const int f = threadIdx.x;
    // ---- prologue (independent of mlp1): stream w2 slice into registers
    float wr[HS], wi[HS];
    {
        const float* w2r = w2 + (size_t)h0 * FDIM;
        const float* w2i = w2 + (size_t)(HID + h0) * FDIM;
        #pragma unroll
        for (int h = 0; h < HS; h++) {
            wr[h] = w2r[(size_t)h * FDIM + f];
            wi[h] = w2i[(size_t)h * FDIM + f];
        }
    }
    cudaGridDependencySynchronize();                 // wait for mlp1 partials
    __shared__ float s1r[BATCH][HS], s1i[BATCH][HS];
    {
        int b = threadIdx.x >> 5, hl = threadIdx.x & 31;   // exactly 256 = 8*32
        int h = h0 + hl;
        float ar = 0.f, ai = 0.f;
        #pragma unroll
        for (int kz = 0; kz < KS1; kz++) {
            ar += g_p1r[kz][b][h];
            ai += g_p1i[kz][b][h];
        }
        ar += b1[h]; ai += b1[HID + h];
        s1r[b][hl] = fmaxf(ar, 0.f);
        s1i[b][hl] = fmaxf(ai, 0.f);
    }
    __syncthreads();
    float ar[BATCH], ai[BATCH];
    #pragma unroll
    for (int b = 0; b < BATCH; b++) { ar[b] = 0.f; ai[b] = 0.f; }
    #pragma unroll
    for (int h = 0; h < HS; h++) {
        #pragma unroll
        for (int b = 0; b < BATCH; b++) {
            float xr = s1r[b][h], xi = s1i[b][h];
            ar[b] = fmaf(xr, wr[h], fmaf(-xi, wi[h], ar[b]));
            ai[b] = fmaf(xi, wr[h], fmaf( xr, wi[h], ai[b]));
        }
    }
    #pragma unroll
    for (int b = 0; b < BATCH; b++) {
        g_p2r[hz][b][f] = ar[b];
        g_p2i[hz][b][f] = ai[b];
    }
}

// ---------------- K4: reduce + softshrink + amp + logits + top-5 ----------
// grid (BATCH), 512 threads. 8-thread group per expert for logits.
__global__ void __launch_bounds__(512)
gate2_kernel(const float* __restrict__ b2, const float* __restrict__ w_gate,
             float* __restrict__ gates_out) {
    cudaTriggerProgrammaticLaunchCompletion();       // release embed's prologue
    int b = blockIdx.x, t = threadIdx.x;
    int g = t >> 3, lg = t & 7;
    // ---- prologue (independent of mlp2): preload this thread's w_gate slice
    float wg[32];
    if (g < NEXP) {
        #pragma unroll
        for (int i = 0; i < 32; i++)
            wg[i] = w_gate[(lg + i * 8) * NEXP + g];
    }
    cudaGridDependencySynchronize();                 // wait for mlp2 partials
    __shared__ float samp[FDIM];
    __shared__ float slog[NEXP];
    if (t < FDIM) {
        int f = t;
        float ar = 0.f, ai = 0.f;
        #pragma unroll
        for (int hz = 0; hz < KS2; hz++) {
            ar += g_p2r[hz][b][f];
            ai += g_p2i[hz][b][f];
        }
        ar += b2[f]; ai += b2[FDIM + f];
        ar = (ar > 0.01f) ? ar - 0.01f : ((ar < -0.01f) ? ar + 0.01f : 0.f);
        ai = (ai > 0.01f) ? ai - 0.01f : ((ai < -0.01f) ? ai + 0.01f : 0.f);
        samp[f] = sqrtf(fmaf(ar, ar, fmaf(ai, ai, 1e-12f)));
    }
    __syncthreads();
    // logits: 64 groups of 8 threads; ALL threads run the shfl (full-warp
    // convergence), groups >= NEXP compute zeros and discard.
    float acc = 0.f;
    if (g < NEXP) {
        #pragma unroll
        for (int i = 0; i < 32; i++)
            acc = fmaf(samp[lg + i * 8], wg[i], acc);
    }
    acc += __shfl_down_sync(0xffffffffu, acc, 4, 8);
    acc += __shfl_down_sync(0xffffffffu, acc, 2, 8);
    acc += __shfl_down_sync(0xffffffffu, acc, 1, 8);
    if (lg == 0 && g < NEXP) slog[g] = acc;
    __syncthreads();
    if (t == 0) {
        float v[NEXP];
        for (int e = 0; e < NEXP; e++) v[e] = slog[e];
        int   idx[TOPK];
        float val[TOPK];
        for (int tt = 0; tt < TOPK; tt++) {
            int bi = 0; float bv = v[0];
            for (int e = 1; e < NEXP; e++) if (v[e] > bv) { bv = v[e]; bi = e; }
            idx[tt] = bi; val[tt] = bv; v[bi] = -3.4e38f;
        }
        float mx = val[0], sum = 0.f, ex[TOPK];
        for (int tt = 0; tt < TOPK; tt++) { ex[tt] = expf(val[tt] - mx); sum += ex[tt]; }
        for (int e = 0; e < NEXP; e++) { gates_out[b * NEXP + e] = 0.f; g_mask[b][e] = 0.f; }
        for (int tt = 0; tt < TOPK; tt++) {
            gates_out[b * NEXP + idx[tt]] = ex[tt] / sum;
            g_mask[b][idx[tt]] = 1.0f;
        }
    }
}

// ---------------- K5: main patch-embedding / zero-fill (PDL prologue) ------
// grid (1657, 8): x = patch-row (reversed: big p first), y = batch.
// 128 threads; each thread owns 4 consecutive d-cols (full 512-d row/block).
__global__ void __launch_bounds__(128)
embed_kernel(const float* __restrict__ x, const float* __restrict__ Wv,
             float* __restrict__ out) {
    const int r = (TOTROWS - 1) - blockIdx.x;     // largest p scheduled first
    const int b = blockIdx.y;
    const int tid = threadIdx.x;
    const int d0 = tid * 4;                        // 0,4,...,508

    // expert lookup (constant-mem scan, uniform) — independent of gates
    int e = 0;
    while (c_OFF[e + 1] <= r) e++;
    const int p = c_P[e];
    const int j = r - c_OFF[e];

    const size_t cstride = (size_t)TOTROWS * DMODEL;
    float* outb = out + ((size_t)(b * NFEAT) * TOTROWS + r) * DMODEL;

    // ---- prologue: stage x patch into smem (independent of gating)
    extern __shared__ float xsm[];                // p*16 floats (<=32KB)
    {
        const float4* x4 = (const float4*)x;
        float4* xsm4 = (float4*)xsm;
        for (int idx = tid; idx < p * 4; idx += 128) {
            int q = idx >> 2, v = idx & 3;
            int l = j * p + q; if (l > SEQL - 1) l = SEQL - 1;   // edge pad
            xsm4[idx] = x4[(((size_t)b * SEQL + l) << 2) + v];
        }
    }
    __syncthreads();

    cudaGridDependencySynchronize();              // wait for gates + tables

    if (g_mask[b][e] == 0.f) {
        // zero-fill 16 rows x 512 cols, float4 (NFEAT*128 = 2048 vec4)
        float4 zz = make_float4(0.f, 0.f, 0.f, 0.f);
        #pragma unroll
        for (int idx = tid; idx < NFEAT * 128; idx += 128) {
            int c = idx >> 7, v = idx & 127;
            *(float4*)(outb + (size_t)c * cstride + v * 4) = zz;
        }
        return;
    }

    float4 acc[NFEAT];
    #pragma unroll
    for (int c = 0; c < NFEAT; c++) acc[c] = make_float4(0.f, 0.f, 0.f, 0.f);

    const float* wv = Wv + (size_t)e * SEQL * DMODEL + d0;
    for (int q = 0; q < p; q++) {
        float4 w = *(const float4*)(wv + (size_t)q * DMODEL);
        const float4* xq4 = (const float4*)(xsm + q * NFEAT);
        float xv[NFEAT];
        *(float4*)(xv +  0) = xq4[0];
        *(float4*)(xv +  4) = xq4[1];
        *(float4*)(xv +  8) = xq4[2];
        *(float4*)(xv + 12) = xq4[3];
        #pragma unroll
        for (int c = 0; c < NFEAT; c++) {
            acc[c].x = fmaf(xv[c], w.x, acc[c].x);
            acc[c].y = fmaf(xv[c], w.y, acc[c].y);
            acc[c].z = fmaf(xv[c], w.z, acc[c].z);
            acc[c].w = fmaf(xv[c], w.w, acc[c].w);
        }
    }

    if (d0 < 256) {
        #pragma unroll
        for (int c = 0; c < NFEAT; c++) {
            float4 pe = *(const float4*)&g_feat[c][d0];
            float4 o = make_float4(acc[c].x + pe.x, acc[c].y + pe.y,
                                   acc[c].z + pe.z, acc[c].w + pe.w);
            *(float4*)(outb + (size_t)c * cstride + d0) = o;
        }
    } else {
        float4 pe = *(const float4*)&g_pos[j][d0 - 256];
        #pragma unroll
        for (int c = 0; c < NFEAT; c++) {
            float4 o = make_float4(acc[c].x + pe.x, acc[c].y + pe.y,
                                   acc[c].z + pe.z, acc[c].w + pe.w);
            *(float4*)(outb + (size_t)c * cstride + d0) = o;
        }
    }
}

// ---------------- launch (PDL chain) ----------------
extern "C" void kernel_launch(void* const* d_in, const int* in_sizes, int n_in,
                              void* d_out, int out_size) {
    const float* x       = (const float*)d_in[0];
    const float* w_start = (const float*)d_in[1];
    const float* b_start = (const float*)d_in[2];
    const float* w1      = (const float*)d_in[3];
    const float* b1      = (const float*)d_in[4];
    const float* w2      = (const float*)d_in[5];
    const float* b2      = (const float*)d_in[6];
    const float* w_gate  = (const float*)d_in[7];
    const float* Wv      = (const float*)d_in[8];
    float* out = (float*)d_out;
    float* gates_out = out + EMB_ELEMS;

    cudaLaunchAttribute pdl[1];
    pdl[0].id = cudaLaunchAttributeProgrammaticStreamSerialization;
    pdl[0].val.programmaticStreamSerializationAllowed = 1;

    gate1_pos_kernel<<<8 + 136, 512>>>(x, w_start, b_start);

    {   cudaLaunchConfig_t cfg = {};
        cfg.gridDim = dim3(HID / 256, KS1); cfg.blockDim = dim3(256);
        cfg.attrs = pdl; cfg.numAttrs = 1;
        cudaLaunchKernelEx(&cfg, mlp1_part_kernel, w1);
    }
    {   cudaLaunchConfig_t cfg = {};
        cfg.gridDim = dim3(KS2); cfg.blockDim = dim3(256);
        cfg.attrs = pdl; cfg.numAttrs = 1;
        cudaLaunchKernelEx(&cfg, mlp2_part_kernel, w2, b1);
    }
    {   cudaLaunchConfig_t cfg = {};
        cfg.gridDim = dim3(BATCH); cfg.blockDim = dim3(512);
        cfg.attrs = pdl; cfg.numAttrs = 1;
        cudaLaunchKernelEx(&cfg, gate2_kernel, b2, w_gate, gates_out);
    }
    {   cudaLaunchConfig_t cfg = {};
        cfg.gridDim = dim3(TOTROWS, BATCH); cfg.blockDim = dim3(128);
        cfg.dynamicSmemBytes = 32768;
        cfg.attrs = pdl; cfg.numAttrs = 1;
        cudaLaunchKernelEx(&cfg, embed_kernel, x, Wv, out);
    }
}

// round 12
// speedup vs baseline: 1.3552x; 1.0133x over previous
#include <cuda_runtime.h>
#include <math.h>

// ---------------- problem constants ----------------
#define BATCH 8
#define SEQL 512
#define NFEAT 16
#define DMODEL 512
#define FDIM 256          // L/2
#define HID 1024          // 4*F
#define NEXP 43
#define TOPK 5
#define TOTROWS 1657
#define EMB_ELEMS 108593152LL   // 8*16*1657*512
#define KS1 16            // k-split for mlp1 (256/16 = 16 per block)
#define KS2 32            // h-split for mlp2 (1024/32 = 32 per block)
#define QCHUNK 128        // embed x-staging chunk (8KB smem)

__constant__ int c_P[NEXP] = {
  2,3,4,5,6,7,8,9,10,11,12,13,14,15,16,17,18,19,20,21,22,23,24,25,26,
  28,30,32,34,36,39,42,46,51,56,64,73,85,102,128,170,256,512};
__constant__ int c_OFF[NEXP+1] = {
  0,256,427,555,658,744,818,882,939,991,1038,1081,1121,1158,1193,1225,
  1256,1285,1312,1338,1363,1387,1410,1432,1453,1473,1492,1510,1526,1542,
  1557,1571,1584,1596,1607,1617,1625,1633,1640,1646,1650,1654,1656,1657};

// ---------------- device scratch ----------------
__device__ float g_xr[BATCH][FDIM];
__device__ float g_xi[BATCH][FDIM];
__device__ float g_p1r[KS1][BATCH][HID];    // mlp1 partials
__device__ float g_p1i[KS1][BATCH][HID];
__device__ float g_p2r[KS2][BATCH][FDIM];   // mlp2 partials
__device__ float g_p2i[KS2][BATCH][FDIM];
__device__ float g_mask[BATCH][NEXP];
__device__ float g_feat[NFEAT][256];   // first half of d_model, depends on c
__device__ float g_pos[256][256];      // second half, depends on patch idx j

// ---------------- K1: gate1 (blocks 0-7, 1024 thr) + pos tables ------------
__global__ void __launch_bounds__(1024)
gate1_pos_kernel(const float* __restrict__ x,
                 const float* __restrict__ w_start,
                 const float* __restrict__ b_start) {
    cudaTriggerProgrammaticLaunchCompletion();   // release mlp1's prologue
    if (blockIdx.x >= 8) {
        // positional tables in fp32 (abs err ~1e-4 << 1e-3 threshold)
        int idx = (blockIdx.x - 8) * 1024 + threadIdx.x;   // 0 .. 69631
        if (idx >= NFEAT * 256 + 256 * 256) return;
        const float L2_10000 = 13.287712379549449f;        // log2(10000)
        if (idx < NFEAT * 256) {
            int c = idx >> 8, i = idx & 255;
            float e2 = (float)(2 * (i >> 1)) * (1.0f / 256.0f);
            float inv = exp2f(-e2 * L2_10000);             // 1/10000^e2
            float a = (float)c * inv;
            g_feat[c][i] = (i & 1) ? cosf(a) : sinf(a);
        } else {
            int k2 = idx - NFEAT * 256;
            int j = k2 >> 8, i = k2 & 255;
            float e2 = (float)(2 * (i >> 1)) * (1.0f / 256.0f);
            float inv = exp2f(-e2 * L2_10000);
            float a = (float)j * inv;
            g_pos[j][i] = (i & 1) ? cosf(a) : sinf(a);
        }
        return;
    }
    // ---- gate1: start_fc + direct rFFT (ortho, drop DC), 1024 threads ----
    __shared__ float xs[SEQL];
    __shared__ float2 tw[SEQL];
    __shared__ float2 ps[1024];
    __shared__ float ws[NFEAT];
    int b = blockIdx.x, t = threadIdx.x;
    if (t < NFEAT) ws[t] = w_start[t];
    if (t < SEQL) {
        float s, c;
        sincospif((float)t * (1.0f / 256.0f), &s, &c);  // angle = 2*pi*t/512
        tw[t] = make_float2(c, s);
    }
    __syncthreads();
    if (t < SEQL) {
        const float* xp = x + (((size_t)b * SEQL + t) << 4);
        float s = b_start[0];
        #pragma unroll
        for (int c = 0; c < NFEAT; c++) s = fmaf(xp[c], ws[c], s);
        xs[t] = s;
    }
    __syncthreads();
    int k  = (t & 255) + 1;                          // k = 1..256 (DC dropped)
    int l0 = (t >> 8) * 128;                         // 0,128,256,384
    float re = 0.f, im = 0.f;
    int m = (k * l0) & 511;
    #pragma unroll 8
    for (int i = 0; i < 128; i++) {
        float xv = xs[l0 + i];
        float2 w = tw[m];
        re = fmaf(xv,  w.x, re);
        im = fmaf(xv, -w.y, im);
        m = (m + k) & 511;
    }
    ps[t] = make_float2(re, im);
    __syncthreads();
    if (t < 256) {
        const float sc = 0.04419417382415922f;       // 1/sqrt(512)
        float2 a = ps[t], bb = ps[t + 256], c = ps[t + 512], d = ps[t + 768];
        g_xr[b][t] = ((a.x + bb.x) + (c.x + d.x)) * sc;
        g_xi[b][t] = ((a.y + bb.y) + (c.y + d.y)) * sc;
    }
}

// ---------------- K2: complex layer 1 partials (PDL: preload w1) ----------
// grid (HID/256=4, KS1=16), 256 threads. Each thread: one h, 16-k slice, 8 b.
__global__ void __launch_bounds__(256)
mlp1_part_kernel(const float* __restrict__ w1) {
    cudaTriggerProgrammaticLaunchCompletion();       // release mlp2's prologue
    const int kz = blockIdx.y;
    const int h  = blockIdx.x * 256 + threadIdx.x;   // 0..1023
    const int KSL = FDIM / KS1;                      // 16
    const int k0 = kz * KSL;
    // ---- prologue (independent of gate1): stream w1 slice into registers
    float wr[KSL], wi[KSL];
    {
        const float* w1r = w1 + (size_t)k0 * HID;
        const float* w1i = w1 + (size_t)(FDIM + k0) * HID;
        #pragma unroll
        for (int k = 0; k < KSL; k++) {
            wr[k] = w1r[(size_t)k * HID + h];
            wi[k] = w1i[(size_t)k * HID + h];
        }
    }
    cudaGridDependencySynchronize();                 // wait for gate1 results
    __shared__ float sxr[BATCH][KSL], sxi[BATCH][KSL];
    if (threadIdx.x < BATCH * KSL) {
        int b = threadIdx.x >> 4, k = threadIdx.x & 15;
        sxr[b][k] = g_xr[b][k0 + k];
        sxi[b][k] = g_xi[b][k0 + k];
    }
    __syncthreads();
    float ar[BATCH], ai[BATCH];
    #pragma unroll
    for (int b = 0; b < BATCH; b++) { ar[b] = 0.f; ai[b] = 0.f; }
    #pragma unroll
    for (int k = 0; k < KSL; k++) {
        #pragma unroll
        for (int b = 0; b < BATCH; b++) {
            float xr = sxr[b][k], xi = sxi[b][k];
            ar[b] = fmaf(xr, wr[k], fmaf(-xi, wi[k], ar[b]));
            ai[b] = fmaf(xi, wr[k], fmaf( xr, wi[k], ai[b]));
        }
    }
    #pragma unroll
    for (int b = 0; b < BATCH; b++) {
        g_p1r[kz][b][h] = ar[b];
        g_p1i[kz][b][h] = ai[b];
    }
}

// ---------------- K3: mlp2 partials (PDL: preload w2) ----------------------
// grid (KS2=32), 256 threads. Stage 1: build o1[h0..h0+32) for 8 batches.
// Stage 2: each thread one f, 32-h slice, 8 batches.
__global__ void __launch_bounds__(256)
mlp2_part_kernel(const float* __restrict__ w2, const float* __restrict__ b1) {
    cudaTriggerProgrammaticLaunchCompletion();       // release gate2's prologue
    const int hz = blockIdx.x;
    const int HS = HID / KS2;                        // 32
    const int h0 = hz * HS;
    const int f = threadIdx.x;
    // ---- prologue (independent of mlp1): stream w2 slice into registers
    float wr[HS], wi[HS];
    {
        const float* w2r = w2 + (size_t)h0 * FDIM;
        const float* w2i = w2 + (size_t)(HID + h0) * FDIM;
        #pragma unroll
        for (int h = 0; h < HS; h++) {
            wr[h] = w2r[(size_t)h * FDIM + f];
            wi[h] = w2i[(size_t)h * FDIM + f];
        }
    }
    cudaGridDependencySynchronize();                 // wait for mlp1 partials
    __shared__ float s1r[BATCH][HS], s1i[BATCH][HS];
    {
        int b = threadIdx.x >> 5, hl = threadIdx.x & 31;   // exactly 256 = 8*32
        int h = h0 + hl;
        float ar = 0.f, ai = 0.f;
        #pragma unroll
        for (int kz = 0; kz < KS1; kz++) {
            ar += g_p1r[kz][b][h];
            ai += g_p1i[kz][b][h];
        }
        ar += b1[h]; ai += b1[HID + h];
        s1r[b][hl] = fmaxf(ar, 0.f);
        s1i[b][hl] = fmaxf(ai, 0.f);
    }
    __syncthreads();
    float ar[BATCH], ai[BATCH];
    #pragma unroll
    for (int b = 0; b < BATCH; b++) { ar[b] = 0.f; ai[b] = 0.f; }
    #pragma unroll
    for (int h = 0; h < HS; h++) {
        #pragma unroll
        for (int b = 0; b < BATCH; b++) {
            float xr = s1r[b][h], xi = s1i[b][h];
            ar[b] = fmaf(xr, wr[h], fmaf(-xi, wi[h], ar[b]));
            ai[b] = fmaf(xi, wr[h], fmaf( xr, wi[h], ai[b]));
        }
    }
    #pragma unroll
    for (int b = 0; b < BATCH; b++) {
        g_p2r[hz][b][f] = ar[b];
        g_p2i[hz][b][f] = ai[b];
    }
}

// ---------------- K4: reduce + softshrink + amp + logits + top-5 ----------
// grid (BATCH), 512 threads. 8-thread group per expert for logits.
__global__ void __launch_bounds__(512)
gate2_kernel(const float* __restrict__ b2, const float* __restrict__ w_gate,
             float* __restrict__ gates_out) {
    cudaTriggerProgrammaticLaunchCompletion();       // release embed's prologue
    int b = blockIdx.x, t = threadIdx.x;
    int g = t >> 3, lg = t & 7;
    // ---- prologue (independent of mlp2): preload this thread's w_gate slice
    float wg[32];
    if (g < NEXP) {
        #pragma unroll
        for (int i = 0; i < 32; i++)
            wg[i] = w_gate[(lg + i * 8) * NEXP + g];
    }
    cudaGridDependencySynchronize();                 // wait for mlp2 partials
    __shared__ float samp[FDIM];
    __shared__ float slog[NEXP];
    if (t < FDIM) {
        int f = t;
        float ar = 0.f, ai = 0.f;
        #pragma unroll
        for (int hz = 0; hz < KS2; hz++) {
            ar += g_p2r[hz][b][f];
            ai += g_p2i[hz][b][f];
        }
        ar += b2[f]; ai += b2[FDIM + f];
        ar = (ar > 0.01f) ? ar - 0.01f : ((ar < -0.01f) ? ar + 0.01f : 0.f);
        ai = (ai > 0.01f) ? ai - 0.01f : ((ai < -0.01f) ? ai + 0.01f : 0.f);
        samp[f] = sqrtf(fmaf(ar, ar, fmaf(ai, ai, 1e-12f)));
    }
    __syncthreads();
    // logits: 64 groups of 8 threads; ALL threads run the shfl (full-warp
    // convergence), groups >= NEXP compute zeros and discard.
    float acc = 0.f;
    if (g < NEXP) {
        #pragma unroll
        for (int i = 0; i < 32; i++)
            acc = fmaf(samp[lg + i * 8], wg[i], acc);
    }
    acc += __shfl_down_sync(0xffffffffu, acc, 4, 8);
    acc += __shfl_down_sync(0xffffffffu, acc, 2, 8);
    acc += __shfl_down_sync(0xffffffffu, acc, 1, 8);
    if (lg == 0 && g < NEXP) slog[g] = acc;
    __syncthreads();
    if (t == 0) {
        float v[NEXP];
        for (int e = 0; e < NEXP; e++) v[e] = slog[e];
        int   idx[TOPK];
        float val[TOPK];
        for (int tt = 0; tt < TOPK; tt++) {
            int bi = 0; float bv = v[0];
            for (int e = 1; e < NEXP; e++) if (v[e] > bv) { bv = v[e]; bi = e; }
            idx[tt] = bi; val[tt] = bv; v[bi] = -3.4e38f;
        }
        float mx = val[0], sum = 0.f, ex[TOPK];
        for (int tt = 0; tt < TOPK; tt++) { ex[tt] = expf(val[tt] - mx); sum += ex[tt]; }
        for (int e = 0; e < NEXP; e++) { gates_out[b * NEXP + e] = 0.f; g_mask[b][e] = 0.f; }
        for (int tt = 0; tt < TOPK; tt++) {
            gates_out[b * NEXP + idx[tt]] = ex[tt] / sum;
            g_mask[b][idx[tt]] = 1.0f;
        }
    }
}

// ---------------- K5: main patch-embedding / zero-fill (chunked smem) ------
// grid (1657, 8): x = patch-row (reversed: big p first), y = batch.
// 128 threads; each thread owns 4 consecutive d-cols. x staged in 8KB chunks
// (static smem) so residency is thread-capped (16 blocks/SM), not smem-capped.
__global__ void __launch_bounds__(128)
embed_kernel(const float* __restrict__ x, const float* __restrict__ Wv,
             float* __restrict__ out) {
    const int r = (TOTROWS - 1) - blockIdx.x;     // largest p scheduled first
    const int b = blockIdx.y;
    const int tid = threadIdx.x;
    const int d0 = tid * 4;                        // 0,4,...,508

    // expert lookup (constant-mem scan, uniform) — independent of gates
    int e = 0;
    while (c_OFF[e + 1] <= r) e++;
    const int p = c_P[e];
    const int j = r - c_OFF[e];

    const size_t cstride = (size_t)TOTROWS * DMODEL;
    float* outb = out + ((size_t)(b * NFEAT) * TOTROWS + r) * DMODEL;

    __shared__ float xsm[QCHUNK * NFEAT];          // 8 KB
    const float4* x4 = (const float4*)x;
    float4* xsm4 = (float4*)xsm;
    const int q0max = (p < QCHUNK ? p : QCHUNK);

    // ---- prologue: stage chunk 0 (independent of gating)
    for (int idx = tid; idx < q0max * 4; idx += 128) {
        int q = idx >> 2, v = idx & 3;
        int l = j * p + q; if (l > SEQL - 1) l = SEQL - 1;     // edge pad
        xsm4[idx] = x4[(((size_t)b * SEQL + l) << 2) + v];
    }
    __syncthreads();

    cudaGridDependencySynchronize();              // wait for gates + tables

    if (g_mask[b][e] == 0.f) {
        // zero-fill 16 rows x 512 cols, float4
        float4 zz = make_float4(0.f, 0.f, 0.f, 0.f);
        #pragma unroll
        for (int c = 0; c < NFEAT; c++)
            *(float4*)(outb + (size_t)c * cstride + d0) = zz;
        return;
    }

    float4 acc[NFEAT];
    #pragma unroll
    for (int c = 0; c < NFEAT; c++) acc[c] = make_float4(0.f, 0.f, 0.f, 0.f);

    const float* wv = Wv + (size_t)e * SEQL * DMODEL + d0;
    const int nchunk = (p + QCHUNK - 1) / QCHUNK;
    for (int ch = 0; ch < nchunk; ch++) {
        const int qbase = ch * QCHUNK;
        const int qcnt = (p - qbase < QCHUNK) ? (p - qbase) : QCHUNK;
        if (ch > 0) {
            __syncthreads();                       // previous compute done
            for (int idx = tid; idx < qcnt * 4; idx += 128) {
                int q = qbase + (idx >> 2), v = idx & 3;
                int l = j * p + q; if (l > SEQL - 1) l = SEQL - 1;
                xsm4[idx] = x4[(((size_t)b * SEQL + l) << 2) + v];
            }
            __syncthreads();
        }
        for (int q = 0; q < qcnt; q++) {
            float4 w = *(const float4*)(wv + (size_t)(qbase + q) * DMODEL);
            const float4* xq4 = (const float4*)(xsm + q * NFEAT);
            float xv[NFEAT];
            *(float4*)(xv +  0) = xq4[0];
            *(float4*)(xv +  4) = xq4[1];
            *(float4*)(xv +  8) = xq4[2];
            *(float4*)(xv + 12) = xq4[3];
            #pragma unroll
            for (int c = 0; c < NFEAT; c++) {
                acc[c].x = fmaf(xv[c], w.x, acc[c].x);
                acc[c].y = fmaf(xv[c], w.y, acc[c].y);
                acc[c].z = fmaf(xv[c], w.z, acc[c].z);
                acc[c].w = fmaf(xv[c], w.w, acc[c].w);
            }
        }
    }

    if (d0 < 256) {
        #pragma unroll
        for (int c = 0; c < NFEAT; c++) {
            float4 pe = *(const float4*)&g_feat[c][d0];
            float4 o = make_float4(acc[c].x + pe.x, acc[c].y + pe.y,
                                   acc[c].z + pe.z, acc[c].w + pe.w);
            *(float4*)(outb + (size_t)c * cstride + d0) = o;
        }
    } else {
        float4 pe = *(const float4*)&g_pos[j][d0 - 256];
        #pragma unroll
        for (int c = 0; c < NFEAT; c++) {
            float4 o = make_float4(acc[c].x + pe.x, acc[c].y + pe.y,
                                   acc[c].z + pe.z, acc[c].w + pe.w);
            *(float4*)(outb + (size_t)c * cstride + d0) = o;
        }
    }
}

// ---------------- launch (PDL chain) ----------------
extern "C" void kernel_launch(void* const* d_in, const int* in_sizes, int n_in,
                              void* d_out, int out_size) {
    const float* x       = (const float*)d_in[0];
    const float* w_start = (const float*)d_in[1];
    const float* b_start = (const float*)d_in[2];
    const float* w1      = (const float*)d_in[3];
    const float* b1      = (const float*)d_in[4];
    const float* w2      = (const float*)d_in[5];
    const float* b2      = (const float*)d_in[6];
    const float* w_gate  = (const float*)d_in[7];
    const float* Wv      = (const float*)d_in[8];
    float* out = (float*)d_out;
    float* gates_out = out + EMB_ELEMS;

    cudaLaunchAttribute pdl[1];
    pdl[0].id = cudaLaunchAttributeProgrammaticStreamSerialization;
    pdl[0].val.programmaticStreamSerializationAllowed = 1;

    gate1_pos_kernel<<<8 + 68, 1024>>>(x, w_start, b_start);

    {   cudaLaunchConfig_t cfg = {};
        cfg.gridDim = dim3(HID / 256, KS1); cfg.blockDim = dim3(256);
        cfg.attrs = pdl; cfg.numAttrs = 1;
        cudaLaunchKernelEx(&cfg, mlp1_part_kernel, w1);
    }
    {   cudaLaunchConfig_t cfg = {};
        cfg.gridDim = dim3(KS2); cfg.blockDim = dim3(256);
        cfg.attrs = pdl; cfg.numAttrs = 1;
        cudaLaunchKernelEx(&cfg, mlp2_part_kernel, w2, b1);
    }
    {   cudaLaunchConfig_t cfg = {};
        cfg.gridDim = dim3(BATCH); cfg.blockDim = dim3(512);
        cfg.attrs = pdl; cfg.numAttrs = 1;
        cudaLaunchKernelEx(&cfg, gate2_kernel, b2, w_gate, gates_out);
    }
    {   cudaLaunchConfig_t cfg = {};
        cfg.gridDim = dim3(TOTROWS, BATCH); cfg.blockDim = dim3(128);
        cfg.attrs = pdl; cfg.numAttrs = 1;
        cudaLaunchKernelEx(&cfg, embed_kernel, x, Wv, out);
    }
}

// round 13
// speedup vs baseline: 1.5539x; 1.1466x over previous
#include <cuda_runtime.h>
#include <math.h>

// ---------------- problem constants ----------------
#define BATCH 8
#define SEQL 512
#define NFEAT 16
#define DMODEL 512
#define FDIM 256          // L/2
#define HID 1024          // 4*F
#define NEXP 43
#define TOPK 5
#define TOTROWS 1657
#define EMB_ELEMS 108593152LL   // 8*16*1657*512
#define KS1 16            // k-split for mlp1 (256/16 = 16 per block)
#define KS2 32            // h-split for mlp2 (1024/32 = 32 per block)
#define QCHUNK 128        // embed x-staging chunk (8KB smem)

__constant__ int c_P[NEXP] = {
  2,3,4,5,6,7,8,9,10,11,12,13,14,15,16,17,18,19,20,21,22,23,24,25,26,
  28,30,32,34,36,39,42,46,51,56,64,73,85,102,128,170,256,512};
__constant__ int c_OFF[NEXP+1] = {
  0,256,427,555,658,744,818,882,939,991,1038,1081,1121,1158,1193,1225,
  1256,1285,1312,1338,1363,1387,1410,1432,1453,1473,1492,1510,1526,1542,
  1557,1571,1584,1596,1607,1617,1625,1633,1640,1646,1650,1654,1656,1657};

// ---------------- device scratch ----------------
__device__ float g_xr[BATCH][FDIM];
__device__ float g_xi[BATCH][FDIM];
__device__ float g_p1r[KS1][BATCH][HID];    // mlp1 partials
__device__ float g_p1i[KS1][BATCH][HID];
__device__ float g_p2r[KS2][BATCH][FDIM];   // mlp2 partials
__device__ float g_p2i[KS2][BATCH][FDIM];
__device__ float g_mask[BATCH][NEXP];
__device__ float g_feat[NFEAT][256];   // first half of d_model, depends on c
__device__ float g_pos[256][256];      // second half, depends on patch idx j

// ---------------- K1: gate1 (blocks 0-7, 1024 thr) + pos tables ------------
__global__ void __launch_bounds__(1024)
gate1_pos_kernel(const float* __restrict__ x,
                 const float* __restrict__ w_start,
                 const float* __restrict__ b_start) {
    cudaTriggerProgrammaticLaunchCompletion();   // release mlp1's prologue
    if (blockIdx.x >= 8) {
        // positional tables in fp32 (abs err ~1e-4 << 1e-3 threshold)
        int idx = (blockIdx.x - 8) * 1024 + threadIdx.x;   // 0 .. 69631
        if (idx >= NFEAT * 256 + 256 * 256) return;
        const float L2_10000 = 13.287712379549449f;        // log2(10000)
        if (idx < NFEAT * 256) {
            int c = idx >> 8, i = idx & 255;
            float e2 = (float)(2 * (i >> 1)) * (1.0f / 256.0f);
            float inv = exp2f(-e2 * L2_10000);             // 1/10000^e2
            float a = (float)c * inv;
            g_feat[c][i] = (i & 1) ? cosf(a) : sinf(a);
        } else {
            int k2 = idx - NFEAT * 256;
            int j = k2 >> 8, i = k2 & 255;
            float e2 = (float)(2 * (i >> 1)) * (1.0f / 256.0f);
            float inv = exp2f(-e2 * L2_10000);
            float a = (float)j * inv;
            g_pos[j][i] = (i & 1) ? cosf(a) : sinf(a);
        }
        return;
    }
    // ---- gate1: start_fc + direct rFFT (ortho, drop DC), 1024 threads ----
    __shared__ float xs[SEQL];
    __shared__ float2 tw[SEQL];
    __shared__ float2 ps[1024];
    __shared__ float ws[NFEAT];
    int b = blockIdx.x, t = threadIdx.x;
    if (t < NFEAT) ws[t] = w_start[t];
    if (t < SEQL) {
        float s, c;
        sincospif((float)t * (1.0f / 256.0f), &s, &c);  // angle = 2*pi*t/512
        tw[t] = make_float2(c, s);
    }
    __syncthreads();
    if (t < SEQL) {
        const float* xp = x + (((size_t)b * SEQL + t) << 4);
        float s = b_start[0];
        #pragma unroll
        for (int c = 0; c < NFEAT; c++) s = fmaf(xp[c], ws[c], s);
        xs[t] = s;
    }
    __syncthreads();
    int k  = (t & 255) + 1;                          // k = 1..256 (DC dropped)
    int l0 = (t >> 8) * 128;                         // 0,128,256,384
    float re = 0.f, im = 0.f;
    int m = (k * l0) & 511;
    #pragma unroll 8
    for (int i = 0; i < 128; i++) {
        float xv = xs[l0 + i];
        float2 w = tw[m];
        re = fmaf(xv,  w.x, re);
        im = fmaf(xv, -w.y, im);
        m = (m + k) & 511;
    }
    ps[t] = make_float2(re, im);
    __syncthreads();
    if (t < 256) {
        const float sc = 0.04419417382415922f;       // 1/sqrt(512)
        float2 a = ps[t], bb = ps[t + 256], c = ps[t + 512], d = ps[t + 768];
        g_xr[b][t] = ((a.x + bb.x) + (c.x + d.x)) * sc;
        g_xi[b][t] = ((a.y + bb.y) + (c.y + d.y)) * sc;
    }
}

// ---------------- K2: complex layer 1 partials (PDL: preload w1) ----------
// grid (HID/256=4, KS1=16), 256 threads. Each thread: one h, 16-k slice, 8 b.
__global__ void __launch_bounds__(256)
mlp1_part_kernel(const float* __restrict__ w1) {
    cudaTriggerProgrammaticLaunchCompletion();       // release mlp2's prologue
    const int kz = blockIdx.y;
    const int h  = blockIdx.x * 256 + threadIdx.x;   // 0..1023
    const int KSL = FDIM / KS1;                      // 16
    const int k0 = kz * KSL;
    // ---- prologue (independent of gate1): stream w1 slice into registers
    float wr[KSL], wi[KSL];
    {
        const float* w1r = w1 + (size_t)k0 * HID;
        const float* w1i = w1 + (size_t)(FDIM + k0) * HID;
        #pragma unroll
        for (int k = 0; k < KSL; k++) {
            wr[k] = w1r[(size_t)k * HID + h];
            wi[k] = w1i[(size_t)k * HID + h];
        }
    }
    cudaGridDependencySynchronize();                 // wait for gate1 results
    __shared__ float sxr[BATCH][KSL], sxi[BATCH][KSL];
    if (threadIdx.x < BATCH * KSL) {
        int b = threadIdx.x >> 4, k = threadIdx.x & 15;
        sxr[b][k] = g_xr[b][k0 + k];
        sxi[b][k] = g_xi[b][k0 + k];
    }
    __syncthreads();
    float ar[BATCH], ai[BATCH];
    #pragma unroll
    for (int b = 0; b < BATCH; b++) { ar[b] = 0.f; ai[b] = 0.f; }
    #pragma unroll
    for (int k = 0; k < KSL; k++) {
        #pragma unroll
        for (int b = 0; b < BATCH; b++) {
            float xr = sxr[b][k], xi = sxi[b][k];
            ar[b] = fmaf(xr, wr[k], fmaf(-xi, wi[k], ar[b]));
            ai[b] = fmaf(xi, wr[k], fmaf( xr, wi[k], ai[b]));
        }
    }
    #pragma unroll
    for (int b = 0; b < BATCH; b++) {
        g_p1r[kz][b][h] = ar[b];
        g_p1i[kz][b][h] = ai[b];
    }
}

// ---------------- K3: mlp2 partials (PDL: preload w2) ----------------------
// grid (KS2=32), 256 threads. Stage 1: build o1[h0..h0+32) for 8 batches.
// Stage 2: each thread one f, 32-h slice, 8 batches.
__global__ void __launch_bounds__(256)
mlp2_part_kernel(const float* __restrict__ w2, const float* __restrict__ b1) {
    cudaTriggerProgrammaticLaunchCompletion();       // release gate2's prologue
    const int hz = blockIdx.x;
    const int HS = HID / KS2;                        // 32
    const int h0 = hz * HS;
    const int f = threadIdx.x;
    // ---- prologue (independent of mlp1): stream w2 slice into registers
    float wr[HS], wi[HS];
    {
        const float* w2r = w2 + (size_t)h0 * FDIM;
        const float* w2i = w2 + (size_t)(HID + h0) * FDIM;
        #pragma unroll
        for (int h = 0; h < HS; h++) {
            wr[h] = w2r[(size_t)h * FDIM + f];
            wi[h] = w2i[(size_t)h * FDIM + f];
        }
    }
    cudaGridDependencySynchronize();                 // wait for mlp1 partials
    __shared__ float s1r[BATCH][HS], s1i[BATCH][HS];
    {
        int b = threadIdx.x >> 5, hl = threadIdx.x & 31;   // exactly 256 = 8*32
        int h = h0 + hl;
        float ar = 0.f, ai = 0.f;
        #pragma unroll
        for (int kz = 0; kz < KS1; kz++) {
            ar += g_p1r[kz][b][h];
            ai += g_p1i[kz][b][h];
        }
        ar += b1[h]; ai += b1[HID + h];
        s1r[b][hl] = fmaxf(ar, 0.f);
        s1i[b][hl] = fmaxf(ai, 0.f);
    }
    __syncthreads();
    float ar[BATCH], ai[BATCH];
    #pragma unroll
    for (int b = 0; b < BATCH; b++) { ar[b] = 0.f; ai[b] = 0.f; }
    #pragma unroll
    for (int h = 0; h < HS; h++) {
        #pragma unroll
        for (int b = 0; b < BATCH; b++) {
            float xr = s1r[b][h], xi = s1i[b][h];
            ar[b] = fmaf(xr, wr[h], fmaf(-xi, wi[h], ar[b]));
            ai[b] = fmaf(xi, wr[h], fmaf( xr, wi[h], ai[b]));
        }
    }
    #pragma unroll
    for (int b = 0; b < BATCH; b++) {
        g_p2r[hz][b][f] = ar[b];
        g_p2i[hz][b][f] = ai[b];
    }
}

// ---------------- K4: reduce + softshrink + amp + logits + top-5 ----------
// grid (BATCH), 512 threads. 8-thread group per expert for logits.
__global__ void __launch_bounds__(512)
gate2_kernel(const float* __restrict__ b2, const float* __restrict__ w_gate,
             float* __restrict__ gates_out) {
    cudaTriggerProgrammaticLaunchCompletion();       // release embed's prologue
    int b = blockIdx.x, t = threadIdx.x;
    int g = t >> 3, lg = t & 7;
    // ---- prologue (independent of mlp2): preload this thread's w_gate slice
    float wg[32];
    if (g < NEXP) {
        #pragma unroll
        for (int i = 0; i < 32; i++)
            wg[i] = w_gate[(lg + i * 8) * NEXP + g];
    }
    cudaGridDependencySynchronize();                 // wait for mlp2 partials
    __shared__ float samp[FDIM];
    __shared__ float slog[NEXP];
    if (t < FDIM) {
        int f = t;
        float ar = 0.f, ai = 0.f;
        #pragma unroll
        for (int hz = 0; hz < KS2; hz++) {
            ar += g_p2r[hz][b][f];
            ai += g_p2i[hz][b][f];
        }
        ar += b2[f]; ai += b2[FDIM + f];
        ar = (ar > 0.01f) ? ar - 0.01f : ((ar < -0.01f) ? ar + 0.01f : 0.f);
        ai = (ai > 0.01f) ? ai - 0.01f : ((ai < -0.01f) ? ai + 0.01f : 0.f);
        samp[f] = sqrtf(fmaf(ar, ar, fmaf(ai, ai, 1e-12f)));
    }
    __syncthreads();
    // logits: 64 groups of 8 threads; ALL threads run the shfl (full-warp
    // convergence), groups >= NEXP compute zeros and discard.
    float acc = 0.f;
    if (g < NEXP) {
        #pragma unroll
        for (int i = 0; i < 32; i++)
            acc = fmaf(samp[lg + i * 8], wg[i], acc);
    }
    acc += __shfl_down_sync(0xffffffffu, acc, 4, 8);
    acc += __shfl_down_sync(0xffffffffu, acc, 2, 8);
    acc += __shfl_down_sync(0xffffffffu, acc, 1, 8);
    if (lg == 0 && g < NEXP) slog[g] = acc;
    __syncthreads();
    if (t == 0) {
        float v[NEXP];
        for (int e = 0; e < NEXP; e++) v[e] = slog[e];
        int   idx[TOPK];
        float val[TOPK];
        for (int tt = 0; tt < TOPK; tt++) {
            int bi = 0; float bv = v[0];
            for (int e = 1; e < NEXP; e++) if (v[e] > bv) { bv = v[e]; bi = e; }
            idx[tt] = bi; val[tt] = bv; v[bi] = -3.4e38f;
        }
        float mx = val[0], sum = 0.f, ex[TOPK];
        for (int tt = 0; tt < TOPK; tt++) { ex[tt] = expf(val[tt] - mx); sum += ex[tt]; }
        for (int e = 0; e < NEXP; e++) { gates_out[b * NEXP + e] = 0.f; g_mask[b][e] = 0.f; }
        for (int tt = 0; tt < TOPK; tt++) {
            gates_out[b * NEXP + idx[tt]] = ex[tt] / sum;
            g_mask[b][idx[tt]] = 1.0f;
        }
    }
}

// ---------------- K5: main patch-embedding / zero-fill (chunked smem) ------
// grid (1657, 8): x = patch-row (reversed: big p first), y = batch.
// 128 threads; each thread owns 4 consecutive d-cols. x staged in 8KB chunks.
// All output stores are streaming (__stcs) — output is write-once, keep L2
// for the reused Wv / x / pos-table lines.
__global__ void __launch_bounds__(128)
embed_kernel(const float* __restrict__ x, const float* __restrict__ Wv,
             float* __restrict__ out) {
    const int r = (TOTROWS - 1) - blockIdx.x;     // largest p scheduled first
    const int b = blockIdx.y;
    const int tid = threadIdx.x;
    const int d0 = tid * 4;                        // 0,4,...,508

    // expert lookup (constant-mem scan, uniform) — independent of gates
    int e = 0;
    while (c_OFF[e + 1] <= r) e++;
    const int p = c_P[e];
    const int j = r - c_OFF[e];

    const size_t cstride = (size_t)TOTROWS * DMODEL;
    float* outb = out + ((size_t)(b * NFEAT) * TOTROWS + r) * DMODEL;

    __shared__ float xsm[QCHUNK * NFEAT];          // 8 KB
    const float4* x4 = (const float4*)x;
    float4* xsm4 = (float4*)xsm;
    const int q0max = (p < QCHUNK ? p : QCHUNK);

    // ---- prologue: stage chunk 0 (independent of gating)
    for (int idx = tid; idx < q0max * 4; idx += 128) {
        int q = idx >> 2, v = idx & 3;
        int l = j * p + q; if (l > SEQL - 1) l = SEQL - 1;     // edge pad
        xsm4[idx] = x4[(((size_t)b * SEQL + l) << 2) + v];
    }
    __syncthreads();

    cudaGridDependencySynchronize();              // wait for gates + tables

    if (g_mask[b][e] == 0.f) {
        // zero-fill: 16 streaming float4 stores per thread
        float4 zz = make_float4(0.f, 0.f, 0.f, 0.f);
        #pragma unroll
        for (int c = 0; c < NFEAT; c++)
            __stcs((float4*)(outb + (size_t)c * cstride + d0), zz);
        return;
    }

    float4 acc[NFEAT];
    #pragma unroll
    for (int c = 0; c < NFEAT; c++) acc[c] = make_float4(0.f, 0.f, 0.f, 0.f);

    const float* wv = Wv + (size_t)e * SEQL * DMODEL + d0;
    const int nchunk = (p + QCHUNK - 1) / QCHUNK;
    for (int ch = 0; ch < nchunk; ch++) {
        const int qbase = ch * QCHUNK;
        const int qcnt = (p - qbase < QCHUNK) ? (p - qbase) : QCHUNK;
        if (ch > 0) {
            __syncthreads();                       // previous compute done
            for (int idx = tid; idx < qcnt * 4; idx += 128) {
                int q = qbase + (idx >> 2), v = idx & 3;
                int l = j * p + q; if (l > SEQL - 1) l = SEQL - 1;
                xsm4[idx] = x4[(((size_t)b * SEQL + l) << 2) + v];
            }
            __syncthreads();
        }
        for (int q = 0; q < qcnt; q++) {
            float4 w = *(const float4*)(wv + (size_t)(qbase + q) * DMODEL);
            const float4* xq4 = (const float4*)(xsm + q * NFEAT);
            float xv[NFEAT];
            *(float4*)(xv +  0) = xq4[0];
            *(float4*)(xv +  4) = xq4[1];
            *(float4*)(xv +  8) = xq4[2];
            *(float4*)(xv + 12) = xq4[3];
            #pragma unroll
            for (int c = 0; c < NFEAT; c++) {
                acc[c].x = fmaf(xv[c], w.x, acc[c].x);
                acc[c].y = fmaf(xv[c], w.y, acc[c].y);
                acc[c].z = fmaf(xv[c], w.z, acc[c].z);
                acc[c].w = fmaf(xv[c], w.w, acc[c].w);
            }
        }
    }

    if (d0 < 256) {
        #pragma unroll
        for (int c = 0; c < NFEAT; c++) {
            float4 pe = *(const float4*)&g_feat[c][d0];
            float4 o = make_float4(acc[c].x + pe.x, acc[c].y + pe.y,
                                   acc[c].z + pe.z, acc[c].w + pe.w);
            __stcs((float4*)(outb + (size_t)c * cstride + d0), o);
        }
    } else {
        float4 pe = *(const float4*)&g_pos[j][d0 - 256];
        #pragma unroll
        for (int c = 0; c < NFEAT; c++) {
            float4 o = make_float4(acc[c].x + pe.x, acc[c].y + pe.y,
                                   acc[c].z + pe.z, acc[c].w + pe.w);
            __stcs((float4*)(outb + (size_t)c * cstride + d0), o);
        }
    }
}

// ---------------- launch (PDL chain) ----------------
extern "C" void kernel_launch(void* const* d_in, const int* in_sizes, int n_in,
                              void* d_out, int out_size) {
    const float* x       = (const float*)d_in[0];
    const float* w_start = (const float*)d_in[1];
    const float* b_start = (const float*)d_in[2];
    const float* w1      = (const float*)d_in[3];
    const float* b1      = (const float*)d_in[4];
    const float* w2      = (const float*)d_in[5];
    const float* b2      = (const float*)d_in[6];
    const float* w_gate  = (const float*)d_in[7];
    const float* Wv      = (const float*)d_in[8];
    float* out = (float*)d_out;
    float* gates_out = out + EMB_ELEMS;

    cudaLaunchAttribute pdl[1];
    pdl[0].id = cudaLaunchAttributeProgrammaticStreamSerialization;
    pdl[0].val.programmaticStreamSerializationAllowed = 1;

    gate1_pos_kernel<<<8 + 68, 1024>>>(x, w_start, b_start);

    {   cudaLaunchConfig_t cfg = {};
        cfg.gridDim = dim3(HID / 256, KS1); cfg.blockDim = dim3(256);
        cfg.attrs = pdl; cfg.numAttrs = 1;
        cudaLaunchKernelEx(&cfg, mlp1_part_kernel, w1);
    }
    {   cudaLaunchConfig_t cfg = {};
        cfg.gridDim = dim3(KS2); cfg.blockDim = dim3(256);
        cfg.attrs = pdl; cfg.numAttrs = 1;
        cudaLaunchKernelEx(&cfg, mlp2_part_kernel, w2, b1);
    }
    {   cudaLaunchConfig_t cfg = {};
        cfg.gridDim = dim3(BATCH); cfg.blockDim = dim3(512);
        cfg.attrs = pdl; cfg.numAttrs = 1;
        cudaLaunchKernelEx(&cfg, gate2_kernel, b2, w_gate, gates_out);
    }
    {   cudaLaunchConfig_t cfg = {};
        cfg.gridDim = dim3(TOTROWS, BATCH); cfg.blockDim = dim3(128);
        cfg.attrs = pdl; cfg.numAttrs = 1;
        cudaLaunchKernelEx(&cfg, embed_kernel, x, Wv, out);
    }
}

// round 14
// speedup vs baseline: 1.5609x; 1.0045x over previous
#include <cuda_runtime.h>
#include <math.h>

// ---------------- problem constants ----------------
#define BATCH 8
#define SEQL 512
#define NFEAT 16
#define DMODEL 512
#define FDIM 256          // L/2
#define HID 1024          // 4*F
#define NEXP 43
#define TOPK 5
#define TOTROWS 1657
#define EMB_ELEMS 108593152LL   // 8*16*1657*512
#define KS1 16            // k-split for mlp1 (256/16 = 16 per block)
#define KS2 32            // h-split for mlp2 (1024/32 = 32 per block)
#define QCHUNK 128        // embed x-staging chunk (8KB smem)

__constant__ int c_P[NEXP] = {
  2,3,4,5,6,7,8,9,10,11,12,13,14,15,16,17,18,19,20,21,22,23,24,25,26,
  28,30,32,34,36,39,42,46,51,56,64,73,85,102,128,170,256,512};
__constant__ int c_OFF[NEXP+1] = {
  0,256,427,555,658,744,818,882,939,991,1038,1081,1121,1158,1193,1225,
  1256,1285,1312,1338,1363,1387,1410,1432,1453,1473,1492,1510,1526,1542,
  1557,1571,1584,1596,1607,1617,1625,1633,1640,1646,1650,1654,1656,1657};

// ---------------- device scratch ----------------
__device__ float g_xr[BATCH][FDIM];
__device__ float g_xi[BATCH][FDIM];
__device__ float g_p1r[KS1][BATCH][HID];    // mlp1 partials
__device__ float g_p1i[KS1][BATCH][HID];
__device__ float g_p2r[KS2][BATCH][FDIM];   // mlp2 partials
__device__ float g_p2i[KS2][BATCH][FDIM];
__device__ float g_mask[BATCH][NEXP];
__device__ float g_feat[NFEAT][256];   // first half of d_model, depends on c
__device__ float g_pos[256][256];      // second half, depends on patch idx j

// ---------------- K1: gate1 (blocks 0-7, 1024 thr) + pos tables ------------
__global__ void __launch_bounds__(1024)
gate1_pos_kernel(const float* __restrict__ x,
                 const float* __restrict__ w_start,
                 const float* __restrict__ b_start) {
    cudaTriggerProgrammaticLaunchCompletion();   // release mlp1's prologue
    if (blockIdx.x >= 8) {
        // positional tables in fp32 (abs err ~1e-4 << 1e-3 threshold)
        int idx = (blockIdx.x - 8) * 1024 + threadIdx.x;   // 0 .. 69631
        if (idx >= NFEAT * 256 + 256 * 256) return;
        const float L2_10000 = 13.287712379549449f;        // log2(10000)
        if (idx < NFEAT * 256) {
            int c = idx >> 8, i = idx & 255;
            float e2 = (float)(2 * (i >> 1)) * (1.0f / 256.0f);
            float inv = exp2f(-e2 * L2_10000);             // 1/10000^e2
            float a = (float)c * inv;
            g_feat[c][i] = (i & 1) ? cosf(a) : sinf(a);
        } else {
            int k2 = idx - NFEAT * 256;
            int j = k2 >> 8, i = k2 & 255;
            float e2 = (float)(2 * (i >> 1)) * (1.0f / 256.0f);
            float inv = exp2f(-e2 * L2_10000);
            float a = (float)j * inv;
            g_pos[j][i] = (i & 1) ? cosf(a) : sinf(a);
        }
        return;
    }
    // ---- gate1: start_fc + direct rFFT (ortho, drop DC), 1024 threads ----
    __shared__ float xs[SEQL];
    __shared__ float2 tw[SEQL];
    __shared__ float2 ps[1024];
    __shared__ float ws[NFEAT];
    int b = blockIdx.x, t = threadIdx.x;
    if (t < NFEAT) ws[t] = w_start[t];
    if (t < SEQL) {
        float s, c;
        sincospif((float)t * (1.0f / 256.0f), &s, &c);  // angle = 2*pi*t/512
        tw[t] = make_float2(c, s);
    }
    __syncthreads();
    if (t < SEQL) {
        const float* xp = x + (((size_t)b * SEQL + t) << 4);
        float s = b_start[0];
        #pragma unroll
        for (int c = 0; c < NFEAT; c++) s = fmaf(xp[c], ws[c], s);
        xs[t] = s;
    }
    __syncthreads();
    int k  = (t & 255) + 1;                          // k = 1..256 (DC dropped)
    int l0 = (t >> 8) * 128;                         // 0,128,256,384
    float re = 0.f, im = 0.f;
    int m = (k * l0) & 511;
    #pragma unroll 8
    for (int i = 0; i < 128; i++) {
        float xv = xs[l0 + i];
        float2 w = tw[m];
        re = fmaf(xv,  w.x, re);
        im = fmaf(xv, -w.y, im);
        m = (m + k) & 511;
    }
    ps[t] = make_float2(re, im);
    __syncthreads();
    if (t < 256) {
        const float sc = 0.04419417382415922f;       // 1/sqrt(512)
        float2 a = ps[t], bb = ps[t + 256], c = ps[t + 512], d = ps[t + 768];
        g_xr[b][t] = ((a.x + bb.x) + (c.x + d.x)) * sc;
        g_xi[b][t] = ((a.y + bb.y) + (c.y + d.y)) * sc;
    }
}

// ---------------- K2: complex layer 1 partials (PDL: preload w1) ----------
// grid (HID/256=4, KS1=16), 256 threads. Each thread: one h, 16-k slice, 8 b.
__global__ void __launch_bounds__(256)
mlp1_part_kernel(const float* __restrict__ w1) {
    cudaTriggerProgrammaticLaunchCompletion();       // release mlp2's prologue
    const int kz = blockIdx.y;
    const int h  = blockIdx.x * 256 + threadIdx.x;   // 0..1023
    const int KSL = FDIM / KS1;                      // 16
    const int k0 = kz * KSL;
    // ---- prologue (independent of gate1): stream w1 slice into registers
    float wr[KSL], wi[KSL];
    {
        const float* w1r = w1 + (size_t)k0 * HID;
        const float* w1i = w1 + (size_t)(FDIM + k0) * HID;
        #pragma unroll
        for (int k = 0; k < KSL; k++) {
            wr[k] = w1r[(size_t)k * HID + h];
            wi[k] = w1i[(size_t)k * HID + h];
        }
    }
    cudaGridDependencySynchronize();                 // wait for gate1 results
    __shared__ float sxr[BATCH][KSL], sxi[BATCH][KSL];
    if (threadIdx.x < BATCH * KSL) {
        int b = threadIdx.x >> 4, k = threadIdx.x & 15;
        sxr[b][k] = g_xr[b][k0 + k];
        sxi[b][k] = g_xi[b][k0 + k];
    }
    __syncthreads();
    float ar[BATCH], ai[BATCH];
    #pragma unroll
    for (int b = 0; b < BATCH; b++) { ar[b] = 0.f; ai[b] = 0.f; }
    #pragma unroll
    for (int k = 0; k < KSL; k++) {
        #pragma unroll
        for (int b = 0; b < BATCH; b++) {
            float xr = sxr[b][k], xi = sxi[b][k];
            ar[b] = fmaf(xr, wr[k], fmaf(-xi, wi[k], ar[b]));
            ai[b] = fmaf(xi, wr[k], fmaf( xr, wi[k], ai[b]));
        }
    }
    #pragma unroll
    for (int b = 0; b < BATCH; b++) {
        g_p1r[kz][b][h] = ar[b];
        g_p1i[kz][b][h] = ai[b];
    }
}

// ---------------- K3: mlp2 partials (PDL: preload w2) ----------------------
// grid (KS2=32), 256 threads. Stage 1: build o1[h0..h0+32) for 8 batches.
// Stage 2: each thread one f, 32-h slice, 8 batches.
__global__ void __launch_bounds__(256)
mlp2_part_kernel(const float* __restrict__ w2, const float* __restrict__ b1) {
    cudaTriggerProgrammaticLaunchCompletion();       // release gate2's prologue
    const int hz = blockIdx.x;
    const int HS = HID / KS2;                        // 32
    const int h0 = hz * HS;
    const int f = threadIdx.x;
    // ---- prologue (independent of mlp1): stream w2 slice into registers
    float wr[HS], wi[HS];
    {
        const float* w2r = w2 + (size_t)h0 * FDIM;
        const float* w2i = w2 + (size_t)(HID + h0) * FDIM;
        #pragma unroll
        for (int h = 0; h < HS; h++) {
            wr[h] = w2r[(size_t)h * FDIM + f];
            wi[h] = w2i[(size_t)h * FDIM + f];
        }
    }
    cudaGridDependencySynchronize();                 // wait for mlp1 partials
    __shared__ float s1r[BATCH][HS], s1i[BATCH][HS];
    {
        int b = threadIdx.x >> 5, hl = threadIdx.x & 31;   // exactly 256 = 8*32
        int h = h0 + hl;
        float ar = 0.f, ai = 0.f;
        #pragma unroll
        for (int kz = 0; kz < KS1; kz++) {
            ar += g_p1r[kz][b][h];
            ai += g_p1i[kz][b][h];
        }
        ar += b1[h]; ai += b1[HID + h];
        s1r[b][hl] = fmaxf(ar, 0.f);
        s1i[b][hl] = fmaxf(ai, 0.f);
    }
    __syncthreads();
    float ar[BATCH], ai[BATCH];
    #pragma unroll
    for (int b = 0; b < BATCH; b++) { ar[b] = 0.f; ai[b] = 0.f; }
    #pragma unroll
    for (int h = 0; h < HS; h++) {
        #pragma unroll
        for (int b = 0; b < BATCH; b++) {
            float xr = s1r[b][h], xi = s1i[b][h];
            ar[b] = fmaf(xr, wr[h], fmaf(-xi, wi[h], ar[b]));
            ai[b] = fmaf(xi, wr[h], fmaf( xr, wi[h], ai[b]));
        }
    }
    #pragma unroll
    for (int b = 0; b < BATCH; b++) {
        g_p2r[hz][b][f] = ar[b];
        g_p2i[hz][b][f] = ai[b];
    }
}

// ---------------- K4: reduce + softshrink + amp + logits + top-5 ----------
// grid (BATCH), 512 threads. Reduce split r/i across thread halves;
// 8-thread group per expert for logits.
__global__ void __launch_bounds__(512)
gate2_kernel(const float* __restrict__ b2, const float* __restrict__ w_gate,
             float* __restrict__ gates_out) {
    cudaTriggerProgrammaticLaunchCompletion();       // release embed's prologue
    int b = blockIdx.x, t = threadIdx.x;
    int g = t >> 3, lg = t & 7;
    // ---- prologue (independent of mlp2): preload this thread's w_gate slice
    float wg[32];
    if (g < NEXP) {
        #pragma unroll
        for (int i = 0; i < 32; i++)
            wg[i] = w_gate[(lg + i * 8) * NEXP + g];
    }
    cudaGridDependencySynchronize();                 // wait for mlp2 partials
    __shared__ float sar[FDIM], sai[FDIM];
    __shared__ float samp[FDIM];
    __shared__ float slog[NEXP];
    {
        int f = t & 255;
        if (t < 256) {
            float ar = 0.f;
            #pragma unroll
            for (int hz = 0; hz < KS2; hz++) ar += g_p2r[hz][b][f];
            sar[f] = ar + b2[f];
        } else {
            float ai = 0.f;
            #pragma unroll
            for (int hz = 0; hz < KS2; hz++) ai += g_p2i[hz][b][f];
            sai[f] = ai + b2[FDIM + f];
        }
    }
    __syncthreads();
    if (t < FDIM) {
        float ar = sar[t], ai = sai[t];
        ar = (ar > 0.01f) ? ar - 0.01f : ((ar < -0.01f) ? ar + 0.01f : 0.f);
        ai = (ai > 0.01f) ? ai - 0.01f : ((ai < -0.01f) ? ai + 0.01f : 0.f);
        samp[t] = sqrtf(fmaf(ar, ar, fmaf(ai, ai, 1e-12f)));
    }
    __syncthreads();
    // logits: 64 groups of 8 threads; ALL threads run the shfl (full-warp
    // convergence), groups >= NEXP compute zeros and discard.
    float acc = 0.f;
    if (g < NEXP) {
        #pragma unroll
        for (int i = 0; i < 32; i++)
            acc = fmaf(samp[lg + i * 8], wg[i], acc);
    }
    acc += __shfl_down_sync(0xffffffffu, acc, 4, 8);
    acc += __shfl_down_sync(0xffffffffu, acc, 2, 8);
    acc += __shfl_down_sync(0xffffffffu, acc, 1, 8);
    if (lg == 0 && g < NEXP) slog[g] = acc;
    __syncthreads();
    if (t == 0) {
        float v[NEXP];
        for (int e = 0; e < NEXP; e++) v[e] = slog[e];
        int   idx[TOPK];
        float val[TOPK];
        for (int tt = 0; tt < TOPK; tt++) {
            int bi = 0; float bv = v[0];
            for (int e = 1; e < NEXP; e++) if (v[e] > bv) { bv = v[e]; bi = e; }
            idx[tt] = bi; val[tt] = bv; v[bi] = -3.4e38f;
        }
        float mx = val[0], sum = 0.f, ex[TOPK];
        for (int tt = 0; tt < TOPK; tt++) { ex[tt] = expf(val[tt] - mx); sum += ex[tt]; }
        for (int e = 0; e < NEXP; e++) { gates_out[b * NEXP + e] = 0.f; g_mask[b][e] = 0.f; }
        for (int tt = 0; tt < TOPK; tt++) {
            gates_out[b * NEXP + idx[tt]] = ex[tt] / sum;
            g_mask[b][idx[tt]] = 1.0f;
        }
    }
}

// ---------------- K5: main patch-embedding / zero-fill (chunked smem) ------
// grid (8, 1657): x = batch (fastest-varying -> the 8 readers of the same Wv
// lines are schedule-adjacent for L2 reuse), y = patch-row (reversed: big p
// first). 128 threads; each thread owns 4 consecutive d-cols. x staged in
// 8KB chunks; output stores streaming (__stcs).
__global__ void __launch_bounds__(128)
embed_kernel(const float* __restrict__ x, const float* __restrict__ Wv,
             float* __restrict__ out) {
    const int b = blockIdx.x;
    const int r = (TOTROWS - 1) - blockIdx.y;     // largest p scheduled first
    const int tid = threadIdx.x;
    const int d0 = tid * 4;                        // 0,4,...,508

    // expert lookup (constant-mem scan, uniform) — independent of gates
    int e = 0;
    while (c_OFF[e + 1] <= r) e++;
    const int p = c_P[e];
    const int j = r - c_OFF[e];

    const size_t cstride = (size_t)TOTROWS * DMODEL;
    float* outb = out + ((size_t)(b * NFEAT) * TOTROWS + r) * DMODEL;

    __shared__ float xsm[QCHUNK * NFEAT];          // 8 KB
    const float4* x4 = (const float4*)x;
    float4* xsm4 = (float4*)xsm;
    const int q0max = (p < QCHUNK ? p : QCHUNK);

    // ---- prologue: stage chunk 0 (independent of gating)
    for (int idx = tid; idx < q0max * 4; idx += 128) {
        int q = idx >> 2, v = idx & 3;
        int l = j * p + q; if (l > SEQL - 1) l = SEQL - 1;     // edge pad
        xsm4[idx] = x4[(((size_t)b * SEQL + l) << 2) + v];
    }
    __syncthreads();

    cudaGridDependencySynchronize();              // wait for gates + tables

    if (g_mask[b][e] == 0.f) {
        // zero-fill: 16 streaming float4 stores per thread
        float4 zz = make_float4(0.f, 0.f, 0.f, 0.f);
        #pragma unroll
        for (int c = 0; c < NFEAT; c++)
            __stcs((float4*)(outb + (size_t)c * cstride + d0), zz);
        return;
    }

    float4 acc[NFEAT];
    #pragma unroll
    for (int c = 0; c < NFEAT; c++) acc[c] = make_float4(0.f, 0.f, 0.f, 0.f);

    const float* wv = Wv + (size_t)e * SEQL * DMODEL + d0;
    const int nchunk = (p + QCHUNK - 1) / QCHUNK;
    for (int ch = 0; ch < nchunk; ch++) {
        const int qbase = ch * QCHUNK;
        const int qcnt = (p - qbase < QCHUNK) ? (p - qbase) : QCHUNK;
        if (ch > 0) {
            __syncthreads();                       // previous compute done
            for (int idx = tid; idx < qcnt * 4; idx += 128) {
                int q = qbase + (idx >> 2), v = idx & 3;
                int l = j * p + q; if (l > SEQL - 1) l = SEQL - 1;
                xsm4[idx] = x4[(((size_t)b * SEQL + l) << 2) + v];
            }
            __syncthreads();
        }
        for (int q = 0; q < qcnt; q++) {
            float4 w = *(const float4*)(wv + (size_t)(qbase + q) * DMODEL);
            const float4* xq4 = (const float4*)(xsm + q * NFEAT);
            float xv[NFEAT];
            *(float4*)(xv +  0) = xq4[0];
            *(float4*)(xv +  4) = xq4[1];
            *(float4*)(xv +  8) = xq4[2];
            *(float4*)(xv + 12) = xq4[3];
            #pragma unroll
            for (int c = 0; c < NFEAT; c++) {
                acc[c].x = fmaf(xv[c], w.x, acc[c].x);
                acc[c].y = fmaf(xv[c], w.y, acc[c].y);
                acc[c].z = fmaf(xv[c], w.z, acc[c].z);
                acc[c].w = fmaf(xv[c], w.w, acc[c].w);
            }
        }
    }

    if (d0 < 256) {
        #pragma unroll
        for (int c = 0; c < NFEAT; c++) {
            float4 pe = *(const float4*)&g_feat[c][d0];
            float4 o = make_float4(acc[c].x + pe.x, acc[c].y + pe.y,
                                   acc[c].z + pe.z, acc[c].w + pe.w);
            __stcs((float4*)(outb + (size_t)c * cstride + d0), o);
        }
    } else {
        float4 pe = *(const float4*)&g_pos[j][d0 - 256];
        #pragma unroll
        for (int c = 0; c < NFEAT; c++) {
            float4 o = make_float4(acc[c].x + pe.x, acc[c].y + pe.y,
                                   acc[c].z + pe.z, acc[c].w + pe.w);
            __stcs((float4*)(outb + (size_t)c * cstride + d0), o);
        }
    }
}

// ---------------- launch (PDL chain) ----------------
extern "C" void kernel_launch(void* const* d_in, const int* in_sizes, int n_in,
                              void* d_out, int out_size) {
    const float* x       = (const float*)d_in[0];
    const float* w_start = (const float*)d_in[1];
    const float* b_start = (const float*)d_in[2];
    const float* w1      = (const float*)d_in[3];
    const float* b1      = (const float*)d_in[4];
    const float* w2      = (const float*)d_in[5];
    const float* b2      = (const float*)d_in[6];
    const float* w_gate  = (const float*)d_in[7];
    const float* Wv      = (const float*)d_in[8];
    float* out = (float*)d_out;
    float* gates_out = out + EMB_ELEMS;

    cudaLaunchAttribute pdl[1];
    pdl[0].id = cudaLaunchAttributeProgrammaticStreamSerialization;
    pdl[0].val.programmaticStreamSerializationAllowed = 1;

    gate1_pos_kernel<<<8 + 68, 1024>>>(x, w_start, b_start);

    {   cudaLaunchConfig_t cfg = {};
        cfg.gridDim = dim3(HID / 256, KS1); cfg.blockDim = dim3(256);
        cfg.attrs = pdl; cfg.numAttrs = 1;
        cudaLaunchKernelEx(&cfg, mlp1_part_kernel, w1);
    }
    {   cudaLaunchConfig_t cfg = {};
        cfg.gridDim = dim3(KS2); cfg.blockDim = dim3(256);
        cfg.attrs = pdl; cfg.numAttrs = 1;
        cudaLaunchKernelEx(&cfg, mlp2_part_kernel, w2, b1);
    }
    {   cudaLaunchConfig_t cfg = {};
        cfg.gridDim = dim3(BATCH); cfg.blockDim = dim3(512);
        cfg.attrs = pdl; cfg.numAttrs = 1;
        cudaLaunchKernelEx(&cfg, gate2_kernel, b2, w_gate, gates_out);
    }
    {   cudaLaunchConfig_t cfg = {};
        cfg.gridDim = dim3(BATCH, TOTROWS); cfg.blockDim = dim3(128);
        cfg.attrs = pdl; cfg.numAttrs = 1;
        cudaLaunchKernelEx(&cfg, embed_kernel, x, Wv, out);
    }
}